// round 2
// baseline (speedup 1.0000x reference)
#include <cuda_runtime.h>
#include <cuda_bf16.h>
#include <math.h>
#include <stdint.h>

#define D_IN    256
#define G_SEG   1024
#define H_HID   128
#define OUT_C   896
#define TM      64
#define THREADS 256
#define NFRAGS  (16*32*32)            /* k-tiles * n-tiles * lanes */

#define WP_BYTES   131072
#define ABF_OFF    131072
#define ABF_BYTES  (TM*512)           /* 64 rows * 256 bf16 cols * 2B  = 32768 */
#define XF_OFF     (ABF_OFF + ABF_BYTES)    /* 163840 */
#define XF_BYTES   (TM*D_IN*4)        /* 65536 */
#define SMALL_OFF  (XF_OFF + XF_BYTES)      /* 229376 */
#define SMEM_BYTES (SMALL_OFF + 2048)       /* 231424 <= 232448 opt-in max */

__device__ int   g_segoff[G_SEG + 1];
__device__ uint2 g_wpack[NFRAGS];

// ---------------------------------------------------------------------------
// Kernel 1: segment offsets from sorted batch. g_segoff[g] = first index with
// batch >= g; g_segoff[G] = n.
// ---------------------------------------------------------------------------
__global__ void seg_offsets_kernel(const int* __restrict__ batch, int n) {
    int i = blockIdx.x * blockDim.x + threadIdx.x;
    if (i >= n) return;
    int b  = batch[i];
    int pb = (i == 0) ? -1 : batch[i - 1];
    for (int g = pb + 1; g <= b; ++g) g_segoff[g] = i;
    if (i == n - 1) {
        for (int g = b + 1; g <= G_SEG; ++g) g_segoff[g] = n;
    }
}

// ---------------------------------------------------------------------------
// Kernel 2: pack Wc = [w1 | lp_w]  (256 x 256) into mma.sync B-fragment order.
// Frag (kt, nt), lane l holds:
//   u.x = {Wc[k0+2c][n] lo, Wc[k0+2c+1][n] hi}
//   u.y = {Wc[k0+8+2c][n] lo, Wc[k0+9+2c][n] hi}
// with c = l&3, n = nt*8 + l/4, k0 = kt*16.
// ---------------------------------------------------------------------------
__global__ void pack_w_kernel(const float* __restrict__ w1,
                              const float* __restrict__ lpw) {
    int e = blockIdx.x * blockDim.x + threadIdx.x;
    if (e >= NFRAGS) return;
    int lane = e & 31;
    int nt   = (e >> 5) & 31;
    int kt   = e >> 10;
    int n  = nt * 8 + (lane >> 2);
    int k0 = kt * 16 + (lane & 3) * 2;
    float v0, v1, v2, v3;
    if (n < H_HID) {
        v0 = w1[(k0    ) * H_HID + n];
        v1 = w1[(k0 + 1) * H_HID + n];
        v2 = w1[(k0 + 8) * H_HID + n];
        v3 = w1[(k0 + 9) * H_HID + n];
    } else {
        int nn = n - H_HID;
        v0 = lpw[(k0    ) * H_HID + nn];
        v1 = lpw[(k0 + 1) * H_HID + nn];
        v2 = lpw[(k0 + 8) * H_HID + nn];
        v3 = lpw[(k0 + 9) * H_HID + nn];
    }
    __nv_bfloat162 p0 = __floats2bfloat162_rn(v0, v1);
    __nv_bfloat162 p1 = __floats2bfloat162_rn(v2, v3);
    uint2 u;
    u.x = *reinterpret_cast<const uint32_t*>(&p0);
    u.y = *reinterpret_cast<const uint32_t*>(&p1);
    g_wpack[e] = u;
}

// ---------------------------------------------------------------------------
// Helpers
// ---------------------------------------------------------------------------
__device__ __forceinline__ float gelu_f(float v) {
    return 0.5f * v * (1.0f + erff(v * 0.70710678118654752f));
}

__device__ __forceinline__ void ldm_x4(uint32_t& r0, uint32_t& r1,
                                       uint32_t& r2, uint32_t& r3,
                                       uint32_t addr) {
    asm volatile("ldmatrix.sync.aligned.m8n8.x4.shared.b16 {%0,%1,%2,%3}, [%4];"
                 : "=r"(r0), "=r"(r1), "=r"(r2), "=r"(r3) : "r"(addr));
}

__device__ __forceinline__ void mma_bf16(float& c0, float& c1, float& c2, float& c3,
                                         uint32_t a0, uint32_t a1, uint32_t a2, uint32_t a3,
                                         uint32_t b0, uint32_t b1) {
    asm volatile("mma.sync.aligned.m16n8k16.row.col.f32.bf16.bf16.f32 "
                 "{%0,%1,%2,%3}, {%4,%5,%6,%7}, {%8,%9}, {%0,%1,%2,%3};"
                 : "+f"(c0), "+f"(c1), "+f"(c2), "+f"(c3)
                 : "r"(a0), "r"(a1), "r"(a2), "r"(a3), "r"(b0), "r"(b1));
}

// ---------------------------------------------------------------------------
// Main kernel: one block per segment. 256 threads = 8 warps arranged 2 (row)
// x 4 (col). Tile TM=64 rows of the segment at a time:
//   pass1: global fp32 x -> col-sum/col-max regs, fp32 smem tile, bf16 smem
//          tile (chunk-XOR swizzled for ldmatrix)
//   mma:   [64x256] @ Wc[256x256] -> gate hidden (cols 0-127), local preact
//          (cols 128-255), fp32 accum
//   epi:   gelu; gate = sum gelu(h)*w2 per row (shfl + smem atomics);
//          local column sums -> persistent registers
//   softmax: online rescale of running (m, d, S)
//   att:   S += exp(gate-m) * x   (fp32 tile from smem)
// ---------------------------------------------------------------------------
__global__ void __launch_bounds__(THREADS, 1)
msr_main_kernel(const float* __restrict__ x,
                const float* __restrict__ b1,
                const float* __restrict__ w2,
                const float* __restrict__ b2p,
                const float* __restrict__ lpb,
                float* __restrict__ out)
{
    extern __shared__ unsigned char sm[];
    uint2* Wp      = reinterpret_cast<uint2*>(sm);
    float* Xf      = reinterpret_cast<float*>(sm + XF_OFF);
    float* gate_s  = reinterpret_cast<float*>(sm + SMALL_OFF);        // [64]
    float* gate_w  = gate_s + 64;                                      // [64]
    float* local_s = gate_w + 64;                                      // [128]
    float* sc      = local_s + 128;  // sc[0]=m, sc[1]=d, sc[2]=scale

    const int g   = blockIdx.x;
    const int tid = threadIdx.x;
    const int s0  = g_segoff[g];
    const int s1  = g_segoff[g + 1];
    const int cnt = s1 - s0;

    float* orow = out + (size_t)g * OUT_C;
    if (cnt <= 0) {
        // empty segment: mean 0, max -inf, att 0, local 0
        for (int c = tid; c < OUT_C; c += THREADS) {
            float v = (c >= 256 && c < 512) ? -INFINITY : 0.0f;
            orow[c] = v;
        }
        return;
    }

    // ---- block init -------------------------------------------------------
    for (int i = tid; i < NFRAGS; i += THREADS) Wp[i] = g_wpack[i];
    if (tid == 0) { sc[0] = -INFINITY; sc[1] = 0.0f; }
    if (tid < 128) local_s[tid] = 0.0f;

    const float b2v = b2p[0];
    const int warp = tid >> 5;
    const int lane = tid & 31;
    const int wr = warp >> 2;          // 0/1  -> row block
    const int wc = warp & 3;           // 0..3 -> col block (64 cols)
    const int colbase = wc * 64;
    const bool isGate = (wc < 2);
    const int mrow0 = wr * 32;

    // per-thread epilogue constants for its 16 (ni,j) columns
    float biasr[16], multr[16];
#pragma unroll
    for (int ni = 0; ni < 8; ++ni) {
#pragma unroll
        for (int j = 0; j < 2; ++j) {
            int col = colbase + ni * 8 + 2 * (lane & 3) + j;
            if (isGate) { biasr[ni * 2 + j] = b1[col]; multr[ni * 2 + j] = w2[col]; }
            else        { biasr[ni * 2 + j] = lpb[col - 128]; multr[ni * 2 + j] = 0.0f; }
        }
    }

    float localacc[16];
#pragma unroll
    for (int i = 0; i < 16; ++i) localacc[i] = 0.0f;

    // pass1 / att-pass roles: thread owns cols (pc, pc+1), rows pr0, pr0+2, ...
    const int pc  = (tid & 127) * 2;
    const int pr0 = tid >> 7;
    float S0 = 0.0f, S1 = 0.0f;
    float csum0 = 0.0f, csum1 = 0.0f;
    float cmax0 = -INFINITY, cmax1 = -INFINITY;

    const uint32_t abf_base = (uint32_t)__cvta_generic_to_shared(sm + ABF_OFF);
    const float* xg = x + (size_t)s0 * D_IN;

    __syncthreads();   // Wp + local_s + sc ready

    // ---- tile loop --------------------------------------------------------
    for (int t0 = 0; t0 < cnt; t0 += TM) {
        const int rows = min(TM, cnt - t0);

        // pass1: load fp32, accumulate sum/max, write fp32 + swizzled bf16 tiles
        for (int r = pr0; r < TM; r += 2) {
            float v0 = 0.0f, v1 = 0.0f;
            if (r < rows) {
                float2 xv = *reinterpret_cast<const float2*>(
                    xg + (size_t)(t0 + r) * D_IN + pc);
                v0 = xv.x; v1 = xv.y;
                *reinterpret_cast<float2*>(Xf + r * D_IN + pc) = xv;
                csum0 += v0; csum1 += v1;
                cmax0 = fmaxf(cmax0, v0); cmax1 = fmaxf(cmax1, v1);
            }
            __nv_bfloat162 bv = __floats2bfloat162_rn(v0, v1);
            uint32_t chunk = (uint32_t)(pc >> 3);
            uint32_t boff  = (uint32_t)r * 512u + ((chunk ^ ((uint32_t)r & 7u)) << 4)
                             + ((uint32_t)pc & 7u) * 2u;
            *reinterpret_cast<__nv_bfloat162*>(sm + ABF_OFF + boff) = bv;
        }
        if (tid < TM) gate_s[tid] = 0.0f;
        __syncthreads();

        // MMA: [64 x 256] x [256 x 256]
        float acc[2][8][4];
#pragma unroll
        for (int mi = 0; mi < 2; ++mi)
#pragma unroll
            for (int ni = 0; ni < 8; ++ni)
#pragma unroll
                for (int q = 0; q < 4; ++q) acc[mi][ni][q] = 0.0f;

#pragma unroll
        for (int kt = 0; kt < 16; ++kt) {
            uint32_t a0[4], a1[4];
            {
                int rr = mrow0 + (lane & 15);
                uint32_t chunk = (uint32_t)(kt * 2 + (lane >> 4));
                uint32_t ad0 = abf_base + (uint32_t)rr * 512u
                               + ((chunk ^ ((uint32_t)rr & 7u)) << 4);
                ldm_x4(a0[0], a0[1], a0[2], a0[3], ad0);
                rr += 16;
                uint32_t ad1 = abf_base + (uint32_t)rr * 512u
                               + ((chunk ^ ((uint32_t)rr & 7u)) << 4);
                ldm_x4(a1[0], a1[1], a1[2], a1[3], ad1);
            }
#pragma unroll
            for (int ni = 0; ni < 8; ++ni) {
                uint2 bb = Wp[((kt * 32) + (wc * 8 + ni)) * 32 + lane];
                mma_bf16(acc[0][ni][0], acc[0][ni][1], acc[0][ni][2], acc[0][ni][3],
                         a0[0], a0[1], a0[2], a0[3], bb.x, bb.y);
                mma_bf16(acc[1][ni][0], acc[1][ni][1], acc[1][ni][2], acc[1][ni][3],
                         a1[0], a1[1], a1[2], a1[3], bb.x, bb.y);
            }
        }

        // epilogue
        if (isGate) {
#pragma unroll
            for (int mi = 0; mi < 2; ++mi) {
#pragma unroll
                for (int q = 0; q < 2; ++q) {
                    int r = mrow0 + 16 * mi + 8 * q + (lane >> 2);
                    float p = 0.0f;
#pragma unroll
                    for (int ni = 0; ni < 8; ++ni) {
#pragma unroll
                        for (int j = 0; j < 2; ++j) {
                            float v = acc[mi][ni][q * 2 + j] + biasr[ni * 2 + j];
                            p += gelu_f(v) * multr[ni * 2 + j];
                        }
                    }
                    p += __shfl_xor_sync(0xffffffffu, p, 1);
                    p += __shfl_xor_sync(0xffffffffu, p, 2);
                    if ((lane & 3) == 0 && r < rows) atomicAdd(&gate_s[r], p);
                }
            }
        } else {
#pragma unroll
            for (int ni = 0; ni < 8; ++ni) {
#pragma unroll
                for (int j = 0; j < 2; ++j) {
                    float p = 0.0f;
#pragma unroll
                    for (int mi = 0; mi < 2; ++mi) {
#pragma unroll
                        for (int q = 0; q < 2; ++q) {
                            int r = mrow0 + 16 * mi + 8 * q + (lane >> 2);
                            if (r < rows)
                                p += gelu_f(acc[mi][ni][q * 2 + j] + biasr[ni * 2 + j]);
                        }
                    }
                    localacc[ni * 2 + j] += p;
                }
            }
        }
        __syncthreads();

        // online softmax update (warp 0)
        if (warp == 0) {
            float g0 = (lane      < rows) ? gate_s[lane]      + b2v : -INFINITY;
            float g1 = (lane + 32 < rows) ? gate_s[lane + 32] + b2v : -INFINITY;
            float tmax = fmaxf(g0, g1);
#pragma unroll
            for (int off = 16; off > 0; off >>= 1)
                tmax = fmaxf(tmax, __shfl_xor_sync(0xffffffffu, tmax, off));
            float mold = sc[0];
            float mnew = fmaxf(mold, tmax);
            float scl  = (mold == -INFINITY) ? 0.0f : expf(mold - mnew);
            float w0 = (lane      < rows) ? expf(g0 - mnew) : 0.0f;
            float w1v = (lane + 32 < rows) ? expf(g1 - mnew) : 0.0f;
            gate_w[lane]      = w0;
            gate_w[lane + 32] = w1v;
            float td = w0 + w1v;
#pragma unroll
            for (int off = 16; off > 0; off >>= 1)
                td += __shfl_xor_sync(0xffffffffu, td, off);
            if (lane == 0) {
                sc[1] = sc[1] * scl + td;
                sc[0] = mnew;
                sc[2] = scl;
            }
        }
        __syncthreads();

        // attention accumulation (fp32 tile from smem)
        {
            float scl = sc[2];
            S0 *= scl; S1 *= scl;
            for (int r = pr0; r < rows; r += 2) {
                float wv = gate_w[r];
                float2 xv = *reinterpret_cast<const float2*>(Xf + r * D_IN + pc);
                S0 = fmaf(wv, xv.x, S0);
                S1 = fmaf(wv, xv.y, S1);
            }
        }
        __syncthreads();
    }

    // ---- final reductions & output ---------------------------------------
    // local: butterfly over the 8 lanes sharing each column, then smem atomics
#pragma unroll
    for (int i = 0; i < 16; ++i) {
        float v = localacc[i];
        v += __shfl_xor_sync(0xffffffffu, v, 4);
        v += __shfl_xor_sync(0xffffffffu, v, 8);
        v += __shfl_xor_sync(0xffffffffu, v, 16);
        localacc[i] = v;
    }
    if (!isGate && (lane >> 2) == 0) {
#pragma unroll
        for (int ni = 0; ni < 8; ++ni) {
#pragma unroll
            for (int j = 0; j < 2; ++j) {
                int cl = colbase - 128 + ni * 8 + 2 * (lane & 3) + j;
                atomicAdd(&local_s[cl], localacc[ni * 2 + j]);
            }
        }
    }
    __syncthreads();

    // stage the t>=128 partials in (now free) Xf
    float* red = Xf;
    if (tid >= 128) {
        red[pc]           = csum0;  red[pc + 1]       = csum1;
        red[256 + pc]     = cmax0;  red[256 + pc + 1] = cmax1;
        red[512 + pc]     = S0;     red[512 + pc + 1] = S1;
    }
    __syncthreads();

    if (tid < 128) {
        float cntf = (float)cnt;
        float d    = sc[1];
        float s0v = csum0 + red[pc];
        float s1v = csum1 + red[pc + 1];
        float m0  = fmaxf(cmax0, red[256 + pc]);
        float m1  = fmaxf(cmax1, red[256 + pc + 1]);
        float a0v = (S0 + red[512 + pc])     / d;
        float a1v = (S1 + red[512 + pc + 1]) / d;
        orow[pc]           = s0v / cntf;
        orow[pc + 1]       = s1v / cntf;
        orow[256 + pc]     = m0;
        orow[256 + pc + 1] = m1;
        orow[512 + pc]     = a0v;
        orow[512 + pc + 1] = a1v;
        orow[768 + tid]    = local_s[tid] / cntf;
    }
}

// ---------------------------------------------------------------------------
// Launch
// ---------------------------------------------------------------------------
extern "C" void kernel_launch(void* const* d_in, const int* in_sizes, int n_in,
                              void* d_out, int out_size) {
    const float* x    = (const float*)d_in[0];
    const int*   bat  = (const int*)  d_in[1];
    const float* w1   = (const float*)d_in[2];
    const float* b1   = (const float*)d_in[3];
    const float* w2   = (const float*)d_in[4];
    const float* b2   = (const float*)d_in[5];
    const float* lpw  = (const float*)d_in[6];
    const float* lpb  = (const float*)d_in[7];
    float* out = (float*)d_out;

    int n = in_sizes[0] / D_IN;

    cudaFuncSetAttribute(msr_main_kernel,
                         cudaFuncAttributeMaxDynamicSharedMemorySize, SMEM_BYTES);

    seg_offsets_kernel<<<(n + 255) / 256, 256>>>(bat, n);
    pack_w_kernel<<<NFRAGS / 256, 256>>>(w1, lpw);
    msr_main_kernel<<<G_SEG, THREADS, SMEM_BYTES>>>(x, b1, w2, b2, lpb, out);
}

// round 3
// speedup vs baseline: 1.2329x; 1.2329x over previous
#include <cuda_runtime.h>
#include <cuda_bf16.h>
#include <math.h>
#include <stdint.h>

#define D_IN    256
#define G_SEG   1024
#define H_HID   128
#define OUT_C   896
#define TM      64
#define THREADS 256
#define NFRAGS  (16*32*32)            /* k-tiles * n-tiles * lanes */

#define WP_BYTES   131072                     /* packed weights (bf16 frags) */
#define XS_OFF     131072                     /* fp32 staging tile (cp.async) */
#define XS_BYTES   (TM*D_IN*4)                /* 65536 */
#define ABF_OFF    (XS_OFF + XS_BYTES)        /* 196608: bf16 A tile (swizzled) */
#define ABF_BYTES  (TM*512)                   /* 32768 */
#define SMALL_OFF  (ABF_OFF + ABF_BYTES)      /* 229376 */
#define SMEM_BYTES (SMALL_OFF + 1040)         /* 230416 <= 231424 known-good */

__device__ int   g_segoff[G_SEG + 1];
__device__ uint2 g_wpack[NFRAGS];

// ---------------------------------------------------------------------------
// Kernel 1: segment offsets from sorted batch.
// ---------------------------------------------------------------------------
__global__ void seg_offsets_kernel(const int* __restrict__ batch, int n) {
    int i = blockIdx.x * blockDim.x + threadIdx.x;
    if (i >= n) return;
    int b  = batch[i];
    int pb = (i == 0) ? -1 : batch[i - 1];
    for (int g = pb + 1; g <= b; ++g) g_segoff[g] = i;
    if (i == n - 1) {
        for (int g = b + 1; g <= G_SEG; ++g) g_segoff[g] = n;
    }
}

// ---------------------------------------------------------------------------
// Kernel 2: pack Wc = [w1 | lp_w]  (256 x 256) into mma.sync B-fragment order.
// ---------------------------------------------------------------------------
__global__ void pack_w_kernel(const float* __restrict__ w1,
                              const float* __restrict__ lpw) {
    int e = blockIdx.x * blockDim.x + threadIdx.x;
    if (e >= NFRAGS) return;
    int lane = e & 31;
    int nt   = (e >> 5) & 31;
    int kt   = e >> 10;
    int n  = nt * 8 + (lane >> 2);
    int k0 = kt * 16 + (lane & 3) * 2;
    float v0, v1, v2, v3;
    if (n < H_HID) {
        v0 = w1[(k0    ) * H_HID + n];
        v1 = w1[(k0 + 1) * H_HID + n];
        v2 = w1[(k0 + 8) * H_HID + n];
        v3 = w1[(k0 + 9) * H_HID + n];
    } else {
        int nn = n - H_HID;
        v0 = lpw[(k0    ) * H_HID + nn];
        v1 = lpw[(k0 + 1) * H_HID + nn];
        v2 = lpw[(k0 + 8) * H_HID + nn];
        v3 = lpw[(k0 + 9) * H_HID + nn];
    }
    __nv_bfloat162 p0 = __floats2bfloat162_rn(v0, v1);
    __nv_bfloat162 p1 = __floats2bfloat162_rn(v2, v3);
    uint2 u;
    u.x = *reinterpret_cast<const uint32_t*>(&p0);
    u.y = *reinterpret_cast<const uint32_t*>(&p1);
    g_wpack[e] = u;
}

// ---------------------------------------------------------------------------
// Helpers
// ---------------------------------------------------------------------------
__device__ __forceinline__ float gelu_f(float v) {
    return 0.5f * v * (1.0f + erff(v * 0.70710678118654752f));
}

__device__ __forceinline__ void ldm_x4(uint32_t& r0, uint32_t& r1,
                                       uint32_t& r2, uint32_t& r3,
                                       uint32_t addr) {
    asm volatile("ldmatrix.sync.aligned.m8n8.x4.shared.b16 {%0,%1,%2,%3}, [%4];"
                 : "=r"(r0), "=r"(r1), "=r"(r2), "=r"(r3) : "r"(addr));
}

__device__ __forceinline__ void mma_bf16(float& c0, float& c1, float& c2, float& c3,
                                         uint32_t a0, uint32_t a1, uint32_t a2, uint32_t a3,
                                         uint32_t b0, uint32_t b1) {
    asm volatile("mma.sync.aligned.m16n8k16.row.col.f32.bf16.bf16.f32 "
                 "{%0,%1,%2,%3}, {%4,%5,%6,%7}, {%8,%9}, {%0,%1,%2,%3};"
                 : "+f"(c0), "+f"(c1), "+f"(c2), "+f"(c3)
                 : "r"(a0), "r"(a1), "r"(a2), "r"(a3), "r"(b0), "r"(b1));
}

__device__ __forceinline__ void cp_async16(uint32_t smem_addr, const void* gptr) {
    asm volatile("cp.async.cg.shared.global [%0], [%1], 16;"
                 :: "r"(smem_addr), "l"(gptr));
}
__device__ __forceinline__ void cp_commit() {
    asm volatile("cp.async.commit_group;");
}
__device__ __forceinline__ void cp_wait0() {
    asm volatile("cp.async.wait_group 0;" ::: "memory");
}

// Issue cp.async for one tile: 4096 16B chunks, chunk = i*THREADS + tid.
// Rows past the segment end are clamped to the last valid row (masked later).
__device__ __forceinline__ void issue_tile(const float* __restrict__ xg,
                                           int base, int cnt, int tid,
                                           uint32_t xs_base) {
    int nrows = cnt - base;            // > 0 guaranteed by caller
    int last  = nrows - 1;
#pragma unroll
    for (int i = 0; i < 16; ++i) {
        int chunk = i * THREADS + tid;        // 0..4095
        int rowL  = chunk >> 6;               // /64 chunks per row
        int col   = (chunk & 63) * 4;         // float index
        int r     = rowL < nrows ? rowL : last;
        const float* src = xg + (size_t)(base + r) * D_IN + col;
        cp_async16(xs_base + (uint32_t)chunk * 16u, src);
    }
    cp_commit();
}

// ---------------------------------------------------------------------------
// Main kernel: one block per segment, 256 threads = 8 warps (2 row x 4 col).
// Pipelined tile loop: cp.async stages tile t+1's fp32 x while tile t runs
// mma/epilogue/softmax/att-replay.
// ---------------------------------------------------------------------------
__global__ void __launch_bounds__(THREADS, 1)
msr_main_kernel(const float* __restrict__ x,
                const float* __restrict__ b1,
                const float* __restrict__ w2,
                const float* __restrict__ b2p,
                const float* __restrict__ lpb,
                float* __restrict__ out)
{
    extern __shared__ unsigned char sm[];
    uint2* Wp      = reinterpret_cast<uint2*>(sm);
    float* Xs      = reinterpret_cast<float*>(sm + XS_OFF);
    float* gate_s  = reinterpret_cast<float*>(sm + SMALL_OFF);        // [64]
    float* gate_w  = gate_s + 64;                                      // [64]
    float* local_s = gate_w + 64;                                      // [128]
    float* sc      = local_s + 128;  // sc[0]=m, sc[1]=d, sc[2]=scale

    const int g   = blockIdx.x;
    const int tid = threadIdx.x;
    const int s0  = g_segoff[g];
    const int s1  = g_segoff[g + 1];
    const int cnt = s1 - s0;

    float* orow = out + (size_t)g * OUT_C;
    if (cnt <= 0) {
        for (int c = tid; c < OUT_C; c += THREADS) {
            float v = (c >= 256 && c < 512) ? -INFINITY : 0.0f;
            orow[c] = v;
        }
        return;
    }

    const uint32_t xs_base  = (uint32_t)__cvta_generic_to_shared(sm + XS_OFF);
    const uint32_t abf_base = (uint32_t)__cvta_generic_to_shared(sm + ABF_OFF);
    const float* xg = x + (size_t)s0 * D_IN;

    // prologue: start fetching tile 0 immediately, then copy weights (L2-hot)
    issue_tile(xg, 0, cnt, tid, xs_base);

    for (int i = tid; i < NFRAGS; i += THREADS) Wp[i] = g_wpack[i];
    if (tid == 0) { sc[0] = -INFINITY; sc[1] = 0.0f; }
    if (tid < 128) local_s[tid] = 0.0f;

    const float b2v = b2p[0];
    const int warp = tid >> 5;
    const int lane = tid & 31;
    const int wr = warp >> 2;          // 0/1  -> row block
    const int wc = warp & 3;           // 0..3 -> col block (64 cols)
    const int colbase = wc * 64;
    const bool isGate = (wc < 2);
    const int mrow0 = wr * 32;

    float biasr[16], multr[16];
#pragma unroll
    for (int ni = 0; ni < 8; ++ni) {
#pragma unroll
        for (int j = 0; j < 2; ++j) {
            int col = colbase + ni * 8 + 2 * (lane & 3) + j;
            if (isGate) { biasr[ni * 2 + j] = b1[col]; multr[ni * 2 + j] = w2[col]; }
            else        { biasr[ni * 2 + j] = lpb[col - 128]; multr[ni * 2 + j] = 0.0f; }
        }
    }

    float localacc[16];
#pragma unroll
    for (int i = 0; i < 16; ++i) localacc[i] = 0.0f;

    // per-thread column ownership for convert / att / output
    const int pc  = (tid & 127) * 2;
    const int pr0 = tid >> 7;
    float S0 = 0.0f, S1 = 0.0f;
    float csum0 = 0.0f, csum1 = 0.0f;
    float cmax0 = -INFINITY, cmax1 = -INFINITY;

    // ---- tile loop --------------------------------------------------------
    for (int t0 = 0; t0 < cnt; t0 += TM) {
        const int rows = min(TM, cnt - t0);

        cp_wait0();
        __syncthreads();   // Xs(t) complete; prev att-replay done (bf16 free)

        // convert: Xs fp32 -> sum/max regs + swizzled bf16 tile
        for (int r = pr0; r < TM; r += 2) {
            float v0 = 0.0f, v1 = 0.0f;
            if (r < rows) {
                float2 xv = *reinterpret_cast<const float2*>(Xs + r * D_IN + pc);
                v0 = xv.x; v1 = xv.y;
                csum0 += v0; csum1 += v1;
                cmax0 = fmaxf(cmax0, v0); cmax1 = fmaxf(cmax1, v1);
            }
            __nv_bfloat162 bv = __floats2bfloat162_rn(v0, v1);
            uint32_t chunk = (uint32_t)(pc >> 3);
            uint32_t boff  = (uint32_t)r * 512u + ((chunk ^ ((uint32_t)r & 7u)) << 4)
                             + ((uint32_t)pc & 7u) * 2u;
            *reinterpret_cast<__nv_bfloat162*>(sm + ABF_OFF + boff) = bv;
        }
        if (tid < TM) gate_s[tid] = 0.0f;
        __syncthreads();   // bf16 ready, Xs free

        // stage next tile while tensor/epilogue work runs
        if (t0 + TM < cnt) issue_tile(xg, t0 + TM, cnt, tid, xs_base);

        // MMA: [64 x 256] x [256 x 256]
        float acc[2][8][4];
#pragma unroll
        for (int mi = 0; mi < 2; ++mi)
#pragma unroll
            for (int ni = 0; ni < 8; ++ni)
#pragma unroll
                for (int q = 0; q < 4; ++q) acc[mi][ni][q] = 0.0f;

#pragma unroll
        for (int kt = 0; kt < 16; ++kt) {
            uint32_t a0[4], a1[4];
            {
                int rr = mrow0 + (lane & 15);
                uint32_t chunk = (uint32_t)(kt * 2 + (lane >> 4));
                uint32_t ad0 = abf_base + (uint32_t)rr * 512u
                               + ((chunk ^ ((uint32_t)rr & 7u)) << 4);
                ldm_x4(a0[0], a0[1], a0[2], a0[3], ad0);
                rr += 16;
                uint32_t ad1 = abf_base + (uint32_t)rr * 512u
                               + ((chunk ^ ((uint32_t)rr & 7u)) << 4);
                ldm_x4(a1[0], a1[1], a1[2], a1[3], ad1);
            }
#pragma unroll
            for (int ni = 0; ni < 8; ++ni) {
                uint2 bb = Wp[((kt * 32) + (wc * 8 + ni)) * 32 + lane];
                mma_bf16(acc[0][ni][0], acc[0][ni][1], acc[0][ni][2], acc[0][ni][3],
                         a0[0], a0[1], a0[2], a0[3], bb.x, bb.y);
                mma_bf16(acc[1][ni][0], acc[1][ni][1], acc[1][ni][2], acc[1][ni][3],
                         a1[0], a1[1], a1[2], a1[3], bb.x, bb.y);
            }
        }

        // epilogue
        if (isGate) {
#pragma unroll
            for (int mi = 0; mi < 2; ++mi) {
#pragma unroll
                for (int q = 0; q < 2; ++q) {
                    int r = mrow0 + 16 * mi + 8 * q + (lane >> 2);
                    float p = 0.0f;
#pragma unroll
                    for (int ni = 0; ni < 8; ++ni) {
#pragma unroll
                        for (int j = 0; j < 2; ++j) {
                            float v = acc[mi][ni][q * 2 + j] + biasr[ni * 2 + j];
                            p += gelu_f(v) * multr[ni * 2 + j];
                        }
                    }
                    p += __shfl_xor_sync(0xffffffffu, p, 1);
                    p += __shfl_xor_sync(0xffffffffu, p, 2);
                    if ((lane & 3) == 0 && r < rows) atomicAdd(&gate_s[r], p);
                }
            }
        } else {
#pragma unroll
            for (int ni = 0; ni < 8; ++ni) {
#pragma unroll
                for (int j = 0; j < 2; ++j) {
                    float p = 0.0f;
#pragma unroll
                    for (int mi = 0; mi < 2; ++mi) {
#pragma unroll
                        for (int q = 0; q < 2; ++q) {
                            int r = mrow0 + 16 * mi + 8 * q + (lane >> 2);
                            if (r < rows)
                                p += gelu_f(acc[mi][ni][q * 2 + j] + biasr[ni * 2 + j]);
                        }
                    }
                    localacc[ni * 2 + j] += p;
                }
            }
        }
        __syncthreads();

        // online softmax update (warp 0)
        if (warp == 0) {
            float g0 = (lane      < rows) ? gate_s[lane]      + b2v : -INFINITY;
            float g1 = (lane + 32 < rows) ? gate_s[lane + 32] + b2v : -INFINITY;
            float tmax = fmaxf(g0, g1);
#pragma unroll
            for (int off = 16; off > 0; off >>= 1)
                tmax = fmaxf(tmax, __shfl_xor_sync(0xffffffffu, tmax, off));
            float mold = sc[0];
            float mnew = fmaxf(mold, tmax);
            float scl  = (mold == -INFINITY) ? 0.0f : expf(mold - mnew);
            float w0 = (lane      < rows) ? expf(g0 - mnew) : 0.0f;
            float w1v = (lane + 32 < rows) ? expf(g1 - mnew) : 0.0f;
            gate_w[lane]      = w0;
            gate_w[lane + 32] = w1v;
            float td = w0 + w1v;
#pragma unroll
            for (int off = 16; off > 0; off >>= 1)
                td += __shfl_xor_sync(0xffffffffu, td, off);
            if (lane == 0) {
                sc[1] = sc[1] * scl + td;
                sc[0] = mnew;
                sc[2] = scl;
            }
        }
        __syncthreads();

        // attention accumulation (bf16 tile replay)
        {
            float scl = sc[2];
            S0 *= scl; S1 *= scl;
            uint32_t chunk = (uint32_t)(pc >> 3);
            for (int r = pr0; r < rows; r += 2) {
                float wv = gate_w[r];
                uint32_t boff = (uint32_t)r * 512u
                                + ((chunk ^ ((uint32_t)r & 7u)) << 4)
                                + ((uint32_t)pc & 7u) * 2u;
                __nv_bfloat162 bv =
                    *reinterpret_cast<const __nv_bfloat162*>(sm + ABF_OFF + boff);
                float2 xv = __bfloat1622float2(bv);
                S0 = fmaf(wv, xv.x, S0);
                S1 = fmaf(wv, xv.y, S1);
            }
        }
        // next loop iteration's cp_wait0+syncthreads separates replay
        // from the next convert's bf16 overwrite
    }
    __syncthreads();

    // ---- final reductions & output ---------------------------------------
#pragma unroll
    for (int i = 0; i < 16; ++i) {
        float v = localacc[i];
        v += __shfl_xor_sync(0xffffffffu, v, 4);
        v += __shfl_xor_sync(0xffffffffu, v, 8);
        v += __shfl_xor_sync(0xffffffffu, v, 16);
        localacc[i] = v;
    }
    if (!isGate && (lane >> 2) == 0) {
#pragma unroll
        for (int ni = 0; ni < 8; ++ni) {
#pragma unroll
            for (int j = 0; j < 2; ++j) {
                int cl = colbase - 128 + ni * 8 + 2 * (lane & 3) + j;
                atomicAdd(&local_s[cl], localacc[ni * 2 + j]);
            }
        }
    }
    __syncthreads();

    // stage the tid>=128 partials in (now free) Xs
    float* red = Xs;
    if (tid >= 128) {
        red[pc]           = csum0;  red[pc + 1]       = csum1;
        red[256 + pc]     = cmax0;  red[256 + pc + 1] = cmax1;
        red[512 + pc]     = S0;     red[512 + pc + 1] = S1;
    }
    __syncthreads();

    if (tid < 128) {
        float cntf = (float)cnt;
        float d    = sc[1];
        float s0v = csum0 + red[pc];
        float s1v = csum1 + red[pc + 1];
        float m0  = fmaxf(cmax0, red[256 + pc]);
        float m1  = fmaxf(cmax1, red[256 + pc + 1]);
        float a0v = (S0 + red[512 + pc])     / d;
        float a1v = (S1 + red[512 + pc + 1]) / d;
        orow[pc]           = s0v / cntf;
        orow[pc + 1]       = s1v / cntf;
        orow[256 + pc]     = m0;
        orow[256 + pc + 1] = m1;
        orow[512 + pc]     = a0v;
        orow[512 + pc + 1] = a1v;
        orow[768 + tid]    = local_s[tid] / cntf;
    }
}

// ---------------------------------------------------------------------------
// Launch
// ---------------------------------------------------------------------------
extern "C" void kernel_launch(void* const* d_in, const int* in_sizes, int n_in,
                              void* d_out, int out_size) {
    const float* x    = (const float*)d_in[0];
    const int*   bat  = (const int*)  d_in[1];
    const float* w1   = (const float*)d_in[2];
    const float* b1   = (const float*)d_in[3];
    const float* w2   = (const float*)d_in[4];
    const float* b2   = (const float*)d_in[5];
    const float* lpw  = (const float*)d_in[6];
    const float* lpb  = (const float*)d_in[7];
    float* out = (float*)d_out;

    int n = in_sizes[0] / D_IN;

    cudaFuncSetAttribute(msr_main_kernel,
                         cudaFuncAttributeMaxDynamicSharedMemorySize, SMEM_BYTES);

    seg_offsets_kernel<<<(n + 255) / 256, 256>>>(bat, n);
    pack_w_kernel<<<NFRAGS / 256, 256>>>(w1, lpw);
    msr_main_kernel<<<G_SEG, THREADS, SMEM_BYTES>>>(x, b1, w2, b2, lpb, out);
}

// round 12
// speedup vs baseline: 1.6683x; 1.3532x over previous
#include <cuda_runtime.h>
#include <cuda_bf16.h>
#include <math.h>
#include <stdint.h>

#define D_IN    256
#define G_SEG   1024
#define H_HID   128
#define OUT_C   896
#define TM      64
#define THREADS 256
#define NFRAGS  (16*32*32)            /* k-tiles * n-tiles * lanes */

#define WP_BYTES   131072                     /* packed weights (bf16 frags) */
#define XS_OFF     131072                     /* fp32 staging tile (cp.async) */
#define XS_BYTES   (TM*D_IN*4)                /* 65536 */
#define ABF_OFF    (XS_OFF + XS_BYTES)        /* 196608: bf16 A tile (swizzled) */
#define ABF_BYTES  (TM*512)                   /* 32768 */
#define SMALL_OFF  (ABF_OFF + ABF_BYTES)      /* 229376 */
#define SMEM_BYTES (SMALL_OFF + 1040)         /* 230416 <= 231424 known-good */

__device__ int   g_segoff[G_SEG + 1];
__device__ uint2 g_wpack[NFRAGS];

// ---------------------------------------------------------------------------
// Kernel 1: segment offsets from sorted batch.
// ---------------------------------------------------------------------------
__global__ void seg_offsets_kernel(const int* __restrict__ batch, int n) {
    int i = blockIdx.x * blockDim.x + threadIdx.x;
    if (i >= n) return;
    int b  = batch[i];
    int pb = (i == 0) ? -1 : batch[i - 1];
    for (int g = pb + 1; g <= b; ++g) g_segoff[g] = i;
    if (i == n - 1) {
        for (int g = b + 1; g <= G_SEG; ++g) g_segoff[g] = n;
    }
}

// ---------------------------------------------------------------------------
// Kernel 2: pack Wc = [w1 | lp_w]  (256 x 256) into mma.sync B-fragment order.
// ---------------------------------------------------------------------------
__global__ void pack_w_kernel(const float* __restrict__ w1,
                              const float* __restrict__ lpw) {
    int e = blockIdx.x * blockDim.x + threadIdx.x;
    if (e >= NFRAGS) return;
    int lane = e & 31;
    int nt   = (e >> 5) & 31;
    int kt   = e >> 10;
    int n  = nt * 8 + (lane >> 2);
    int k0 = kt * 16 + (lane & 3) * 2;
    float v0, v1, v2, v3;
    if (n < H_HID) {
        v0 = w1[(k0    ) * H_HID + n];
        v1 = w1[(k0 + 1) * H_HID + n];
        v2 = w1[(k0 + 8) * H_HID + n];
        v3 = w1[(k0 + 9) * H_HID + n];
    } else {
        int nn = n - H_HID;
        v0 = lpw[(k0    ) * H_HID + nn];
        v1 = lpw[(k0 + 1) * H_HID + nn];
        v2 = lpw[(k0 + 8) * H_HID + nn];
        v3 = lpw[(k0 + 9) * H_HID + nn];
    }
    __nv_bfloat162 p0 = __floats2bfloat162_rn(v0, v1);
    __nv_bfloat162 p1 = __floats2bfloat162_rn(v2, v3);
    uint2 u;
    u.x = *reinterpret_cast<const uint32_t*>(&p0);
    u.y = *reinterpret_cast<const uint32_t*>(&p1);
    g_wpack[e] = u;
}

// ---------------------------------------------------------------------------
// Helpers
// ---------------------------------------------------------------------------
// tanh-form GELU using HW tanh.approx (pre-activations here have |v| < ~2,
// where the deviation from erf-form is <= ~3e-4 absolute).
__device__ __forceinline__ float gelu_f(float v) {
    float u = 0.79788456080286536f * fmaf(0.044715f * v, v * v, v);
    float t;
    asm("tanh.approx.f32 %0, %1;" : "=f"(t) : "f"(u));
    return 0.5f * v * (1.0f + t);
}

__device__ __forceinline__ void ldm_x4(uint32_t& r0, uint32_t& r1,
                                       uint32_t& r2, uint32_t& r3,
                                       uint32_t addr) {
    asm volatile("ldmatrix.sync.aligned.m8n8.x4.shared.b16 {%0,%1,%2,%3}, [%4];"
                 : "=r"(r0), "=r"(r1), "=r"(r2), "=r"(r3) : "r"(addr));
}

__device__ __forceinline__ void mma_bf16(float& c0, float& c1, float& c2, float& c3,
                                         uint32_t a0, uint32_t a1, uint32_t a2, uint32_t a3,
                                         uint32_t b0, uint32_t b1) {
    asm volatile("mma.sync.aligned.m16n8k16.row.col.f32.bf16.bf16.f32 "
                 "{%0,%1,%2,%3}, {%4,%5,%6,%7}, {%8,%9}, {%0,%1,%2,%3};"
                 : "+f"(c0), "+f"(c1), "+f"(c2), "+f"(c3)
                 : "r"(a0), "r"(a1), "r"(a2), "r"(a3), "r"(b0), "r"(b1));
}

__device__ __forceinline__ void cp_async16(uint32_t smem_addr, const void* gptr) {
    asm volatile("cp.async.cg.shared.global [%0], [%1], 16;"
                 :: "r"(smem_addr), "l"(gptr));
}
__device__ __forceinline__ void cp_commit() {
    asm volatile("cp.async.commit_group;");
}
__device__ __forceinline__ void cp_wait0() {
    asm volatile("cp.async.wait_group 0;" ::: "memory");
}

// Issue cp.async for one tile: 4096 16B chunks, chunk = i*THREADS + tid.
// Rows past the segment end are clamped to the last valid row (masked later).
__device__ __forceinline__ void issue_tile(const float* __restrict__ xg,
                                           int base, int cnt, int tid,
                                           uint32_t xs_base) {
    int nrows = cnt - base;            // > 0 guaranteed by caller
    int last  = nrows - 1;
#pragma unroll
    for (int i = 0; i < 16; ++i) {
        int chunk = i * THREADS + tid;        // 0..4095
        int rowL  = chunk >> 6;               // /64 chunks per row
        int col   = (chunk & 63) * 4;         // float index
        int r     = rowL < nrows ? rowL : last;
        const float* src = xg + (size_t)(base + r) * D_IN + col;
        cp_async16(xs_base + (uint32_t)chunk * 16u, src);
    }
    cp_commit();
}

// ---------------------------------------------------------------------------
// Main kernel: one block per segment, 256 threads = 8 warps (2 row x 4 col).
// Pipelined tile loop: cp.async stages tile t+1's fp32 x while tile t runs
// mma/epilogue/softmax/att-replay.
// ---------------------------------------------------------------------------
__global__ void __launch_bounds__(THREADS, 1)
msr_main_kernel(const float* __restrict__ x,
                const float* __restrict__ b1,
                const float* __restrict__ w2,
                const float* __restrict__ b2p,
                const float* __restrict__ lpb,
                float* __restrict__ out)
{
    extern __shared__ unsigned char sm[];
    uint2* Wp      = reinterpret_cast<uint2*>(sm);
    float* Xs      = reinterpret_cast<float*>(sm + XS_OFF);
    float* gate_s  = reinterpret_cast<float*>(sm + SMALL_OFF);        // [64]
    float* gate_w  = gate_s + 64;                                      // [64]
    float* local_s = gate_w + 64;                                      // [128]
    float* sc      = local_s + 128;  // sc[0]=m, sc[1]=d, sc[2]=scale

    const int g   = blockIdx.x;
    const int tid = threadIdx.x;
    const int s0  = g_segoff[g];
    const int s1  = g_segoff[g + 1];
    const int cnt = s1 - s0;

    float* orow = out + (size_t)g * OUT_C;
    if (cnt <= 0) {
        for (int c = tid; c < OUT_C; c += THREADS) {
            float v = (c >= 256 && c < 512) ? -INFINITY : 0.0f;
            orow[c] = v;
        }
        return;
    }

    const uint32_t xs_base  = (uint32_t)__cvta_generic_to_shared(sm + XS_OFF);
    const uint32_t abf_base = (uint32_t)__cvta_generic_to_shared(sm + ABF_OFF);
    const float* xg = x + (size_t)s0 * D_IN;

    // prologue: start fetching tile 0 immediately, then copy weights (L2-hot)
    issue_tile(xg, 0, cnt, tid, xs_base);

    for (int i = tid; i < NFRAGS; i += THREADS) Wp[i] = g_wpack[i];
    if (tid == 0) { sc[0] = -INFINITY; sc[1] = 0.0f; }
    if (tid < 128) local_s[tid] = 0.0f;

    const float b2v = b2p[0];
    const int warp = tid >> 5;
    const int lane = tid & 31;
    const int wr = warp >> 2;          // 0/1  -> row block
    const int wc = warp & 3;           // 0..3 -> col block (64 cols)
    const int colbase = wc * 64;
    const bool isGate = (wc < 2);
    const int mrow0 = wr * 32;

    float biasr[16], multr[16];
#pragma unroll
    for (int ni = 0; ni < 8; ++ni) {
#pragma unroll
        for (int j = 0; j < 2; ++j) {
            int col = colbase + ni * 8 + 2 * (lane & 3) + j;
            if (isGate) { biasr[ni * 2 + j] = b1[col]; multr[ni * 2 + j] = w2[col]; }
            else        { biasr[ni * 2 + j] = lpb[col - 128]; multr[ni * 2 + j] = 0.0f; }
        }
    }

    float localacc[16];
#pragma unroll
    for (int i = 0; i < 16; ++i) localacc[i] = 0.0f;

    // per-thread column ownership for convert / att / output
    const int pc  = (tid & 127) * 2;
    const int pr0 = tid >> 7;
    float S0 = 0.0f, S1 = 0.0f;
    float csum0 = 0.0f, csum1 = 0.0f;
    float cmax0 = -INFINITY, cmax1 = -INFINITY;

    // ---- tile loop --------------------------------------------------------
    for (int t0 = 0; t0 < cnt; t0 += TM) {
        const int rows = min(TM, cnt - t0);

        cp_wait0();
        __syncthreads();   // Xs(t) complete; prev att-replay done (bf16 free)

        // convert: Xs fp32 -> sum/max regs + swizzled bf16 tile
        for (int r = pr0; r < TM; r += 2) {
            float v0 = 0.0f, v1 = 0.0f;
            if (r < rows) {
                float2 xv = *reinterpret_cast<const float2*>(Xs + r * D_IN + pc);
                v0 = xv.x; v1 = xv.y;
                csum0 += v0; csum1 += v1;
                cmax0 = fmaxf(cmax0, v0); cmax1 = fmaxf(cmax1, v1);
            }
            __nv_bfloat162 bv = __floats2bfloat162_rn(v0, v1);
            uint32_t chunk = (uint32_t)(pc >> 3);
            uint32_t boff  = (uint32_t)r * 512u + ((chunk ^ ((uint32_t)r & 7u)) << 4)
                             + ((uint32_t)pc & 7u) * 2u;
            *reinterpret_cast<__nv_bfloat162*>(sm + ABF_OFF + boff) = bv;
        }
        if (tid < TM) gate_s[tid] = 0.0f;
        __syncthreads();   // bf16 ready, Xs free

        // stage next tile while tensor/epilogue work runs
        if (t0 + TM < cnt) issue_tile(xg, t0 + TM, cnt, tid, xs_base);

        // MMA: [64 x 256] x [256 x 256]
        float acc[2][8][4];
#pragma unroll
        for (int mi = 0; mi < 2; ++mi)
#pragma unroll
            for (int ni = 0; ni < 8; ++ni)
#pragma unroll
                for (int q = 0; q < 4; ++q) acc[mi][ni][q] = 0.0f;

#pragma unroll
        for (int kt = 0; kt < 16; ++kt) {
            uint32_t a0[4], a1[4];
            {
                int rr = mrow0 + (lane & 15);
                uint32_t chunk = (uint32_t)(kt * 2 + (lane >> 4));
                uint32_t ad0 = abf_base + (uint32_t)rr * 512u
                               + ((chunk ^ ((uint32_t)rr & 7u)) << 4);
                ldm_x4(a0[0], a0[1], a0[2], a0[3], ad0);
                rr += 16;
                uint32_t ad1 = abf_base + (uint32_t)rr * 512u
                               + ((chunk ^ ((uint32_t)rr & 7u)) << 4);
                ldm_x4(a1[0], a1[1], a1[2], a1[3], ad1);
            }
#pragma unroll
            for (int ni = 0; ni < 8; ++ni) {
                uint2 bb = Wp[((kt * 32) + (wc * 8 + ni)) * 32 + lane];
                mma_bf16(acc[0][ni][0], acc[0][ni][1], acc[0][ni][2], acc[0][ni][3],
                         a0[0], a0[1], a0[2], a0[3], bb.x, bb.y);
                mma_bf16(acc[1][ni][0], acc[1][ni][1], acc[1][ni][2], acc[1][ni][3],
                         a1[0], a1[1], a1[2], a1[3], bb.x, bb.y);
            }
        }

        // epilogue
        if (isGate) {
#pragma unroll
            for (int mi = 0; mi < 2; ++mi) {
#pragma unroll
                for (int q = 0; q < 2; ++q) {
                    int r = mrow0 + 16 * mi + 8 * q + (lane >> 2);
                    float p = 0.0f;
#pragma unroll
                    for (int ni = 0; ni < 8; ++ni) {
#pragma unroll
                        for (int j = 0; j < 2; ++j) {
                            float v = acc[mi][ni][q * 2 + j] + biasr[ni * 2 + j];
                            p += gelu_f(v) * multr[ni * 2 + j];
                        }
                    }
                    p += __shfl_xor_sync(0xffffffffu, p, 1);
                    p += __shfl_xor_sync(0xffffffffu, p, 2);
                    if ((lane & 3) == 0 && r < rows) atomicAdd(&gate_s[r], p);
                }
            }
        } else {
#pragma unroll
            for (int ni = 0; ni < 8; ++ni) {
#pragma unroll
                for (int j = 0; j < 2; ++j) {
                    float p = 0.0f;
#pragma unroll
                    for (int mi = 0; mi < 2; ++mi) {
#pragma unroll
                        for (int q = 0; q < 2; ++q) {
                            int r = mrow0 + 16 * mi + 8 * q + (lane >> 2);
                            if (r < rows)
                                p += gelu_f(acc[mi][ni][q * 2 + j] + biasr[ni * 2 + j]);
                        }
                    }
                    localacc[ni * 2 + j] += p;
                }
            }
        }
        __syncthreads();

        // online softmax update (warp 0)
        if (warp == 0) {
            float g0 = (lane      < rows) ? gate_s[lane]      + b2v : -INFINITY;
            float g1 = (lane + 32 < rows) ? gate_s[lane + 32] + b2v : -INFINITY;
            float tmax = fmaxf(g0, g1);
#pragma unroll
            for (int off = 16; off > 0; off >>= 1)
                tmax = fmaxf(tmax, __shfl_xor_sync(0xffffffffu, tmax, off));
            float mold = sc[0];
            float mnew = fmaxf(mold, tmax);
            float scl  = (mold == -INFINITY) ? 0.0f : __expf(mold - mnew);
            float w0 = (lane      < rows) ? __expf(g0 - mnew) : 0.0f;
            float w1v = (lane + 32 < rows) ? __expf(g1 - mnew) : 0.0f;
            gate_w[lane]      = w0;
            gate_w[lane + 32] = w1v;
            float td = w0 + w1v;
#pragma unroll
            for (int off = 16; off > 0; off >>= 1)
                td += __shfl_xor_sync(0xffffffffu, td, off);
            if (lane == 0) {
                sc[1] = sc[1] * scl + td;
                sc[0] = mnew;
                sc[2] = scl;
            }
        }
        __syncthreads();

        // attention accumulation (bf16 tile replay)
        {
            float scl = sc[2];
            S0 *= scl; S1 *= scl;
            uint32_t chunk = (uint32_t)(pc >> 3);
            for (int r = pr0; r < rows; r += 2) {
                float wv = gate_w[r];
                uint32_t boff = (uint32_t)r * 512u
                                + ((chunk ^ ((uint32_t)r & 7u)) << 4)
                                + ((uint32_t)pc & 7u) * 2u;
                __nv_bfloat162 bv =
                    *reinterpret_cast<const __nv_bfloat162*>(sm + ABF_OFF + boff);
                float2 xv = __bfloat1622float2(bv);
                S0 = fmaf(wv, xv.x, S0);
                S1 = fmaf(wv, xv.y, S1);
            }
        }
        // next loop iteration's cp_wait0+syncthreads separates replay
        // from the next convert's bf16 overwrite
    }
    __syncthreads();

    // ---- final reductions & output ---------------------------------------
#pragma unroll
    for (int i = 0; i < 16; ++i) {
        float v = localacc[i];
        v += __shfl_xor_sync(0xffffffffu, v, 4);
        v += __shfl_xor_sync(0xffffffffu, v, 8);
        v += __shfl_xor_sync(0xffffffffu, v, 16);
        localacc[i] = v;
    }
    if (!isGate && (lane >> 2) == 0) {
#pragma unroll
        for (int ni = 0; ni < 8; ++ni) {
#pragma unroll
            for (int j = 0; j < 2; ++j) {
                int cl = colbase - 128 + ni * 8 + 2 * (lane & 3) + j;
                atomicAdd(&local_s[cl], localacc[ni * 2 + j]);
            }
        }
    }
    __syncthreads();

    // stage the tid>=128 partials in (now free) Xs
    float* red = Xs;
    if (tid >= 128) {
        red[pc]           = csum0;  red[pc + 1]       = csum1;
        red[256 + pc]     = cmax0;  red[256 + pc + 1] = cmax1;
        red[512 + pc]     = S0;     red[512 + pc + 1] = S1;
    }
    __syncthreads();

    if (tid < 128) {
        float cntf = (float)cnt;
        float d    = sc[1];
        float s0v = csum0 + red[pc];
        float s1v = csum1 + red[pc + 1];
        float m0  = fmaxf(cmax0, red[256 + pc]);
        float m1  = fmaxf(cmax1, red[256 + pc + 1]);
        float a0v = (S0 + red[512 + pc])     / d;
        float a1v = (S1 + red[512 + pc + 1]) / d;
        orow[pc]           = s0v / cntf;
        orow[pc + 1]       = s1v / cntf;
        orow[256 + pc]     = m0;
        orow[256 + pc + 1] = m1;
        orow[512 + pc]     = a0v;
        orow[512 + pc + 1] = a1v;
        orow[768 + tid]    = local_s[tid] / cntf;
    }
}

// ---------------------------------------------------------------------------
// Launch
// ---------------------------------------------------------------------------
extern "C" void kernel_launch(void* const* d_in, const int* in_sizes, int n_in,
                              void* d_out, int out_size) {
    const float* x    = (const float*)d_in[0];
    const int*   bat  = (const int*)  d_in[1];
    const float* w1   = (const float*)d_in[2];
    const float* b1   = (const float*)d_in[3];
    const float* w2   = (const float*)d_in[4];
    const float* b2   = (const float*)d_in[5];
    const float* lpw  = (const float*)d_in[6];
    const float* lpb  = (const float*)d_in[7];
    float* out = (float*)d_out;

    int n = in_sizes[0] / D_IN;

    cudaFuncSetAttribute(msr_main_kernel,
                         cudaFuncAttributeMaxDynamicSharedMemorySize, SMEM_BYTES);

    seg_offsets_kernel<<<(n + 255) / 256, 256>>>(bat, n);
    pack_w_kernel<<<NFRAGS / 256, 256>>>(w1, lpw);
    msr_main_kernel<<<G_SEG, THREADS, SMEM_BYTES>>>(x, b1, w2, b2, lpb, out);
}

// round 14
// speedup vs baseline: 1.7205x; 1.0313x over previous
#include <cuda_runtime.h>
#include <cuda_bf16.h>
#include <math.h>
#include <stdint.h>

#define D_IN    256
#define G_SEG   1024
#define H_HID   128
#define OUT_C   896
#define TM      64
#define THREADS 256
#define NFRAGS  (16*32*32)            /* k-tiles * n-tiles * lanes */

#define WP_BYTES   131072                     /* packed weights (bf16 frags) */
#define XS_OFF     131072                     /* fp32 staging tile (cp.async) */
#define XS_BYTES   (TM*D_IN*4)                /* 65536 */
#define ABF_OFF    (XS_OFF + XS_BYTES)        /* 196608: bf16 A tile (swizzled) */
#define ABF_BYTES  (TM*512)                   /* 32768 */
#define SMALL_OFF  (ABF_OFF + ABF_BYTES)      /* 229376 */
/* small region: gp[128] (512B) | gate_w[64] (256B) | local_s[128] (512B) |
   dstage[8] (32B)  => 1312B */
#define SMEM_BYTES (SMALL_OFF + 2048)         /* 231424 known-good */

__device__ int   g_segoff[G_SEG + 1];
__device__ uint2 g_wpack[NFRAGS];

// ---------------------------------------------------------------------------
// Prep kernel (single launch): weight frag pack + segment offsets.
// ---------------------------------------------------------------------------
__global__ void prep_kernel(const int* __restrict__ batch, int n,
                            const float* __restrict__ w1,
                            const float* __restrict__ lpw) {
    int idx = blockIdx.x * blockDim.x + threadIdx.x;
    if (idx < NFRAGS) {
        int lane = idx & 31;
        int nt   = (idx >> 5) & 31;
        int kt   = idx >> 10;
        int nn = nt * 8 + (lane >> 2);
        int k0 = kt * 16 + (lane & 3) * 2;
        const float* W = (nn < H_HID) ? w1 : lpw;
        int nc = nn & 127;
        float v0 = W[(k0    ) * H_HID + nc];
        float v1 = W[(k0 + 1) * H_HID + nc];
        float v2 = W[(k0 + 8) * H_HID + nc];
        float v3 = W[(k0 + 9) * H_HID + nc];
        __nv_bfloat162 p0 = __floats2bfloat162_rn(v0, v1);
        __nv_bfloat162 p1 = __floats2bfloat162_rn(v2, v3);
        uint2 u;
        u.x = *reinterpret_cast<const uint32_t*>(&p0);
        u.y = *reinterpret_cast<const uint32_t*>(&p1);
        g_wpack[idx] = u;
    } else {
        int i = idx - NFRAGS;
        if (i < n) {
            int b  = batch[i];
            int pb = (i == 0) ? -1 : batch[i - 1];
            for (int s = pb + 1; s <= b; ++s) g_segoff[s] = i;
            if (i == n - 1)
                for (int s = b + 1; s <= G_SEG; ++s) g_segoff[s] = n;
        }
    }
}

// ---------------------------------------------------------------------------
// Helpers
// ---------------------------------------------------------------------------
// tanh-form GELU using HW tanh.approx (pre-activations here have |v| < ~2).
__device__ __forceinline__ float gelu_f(float v) {
    float u = 0.79788456080286536f * fmaf(0.044715f * v, v * v, v);
    float t;
    asm("tanh.approx.f32 %0, %1;" : "=f"(t) : "f"(u));
    return 0.5f * v * (1.0f + t);
}

__device__ __forceinline__ void ldm_x4(uint32_t& r0, uint32_t& r1,
                                       uint32_t& r2, uint32_t& r3,
                                       uint32_t addr) {
    asm volatile("ldmatrix.sync.aligned.m8n8.x4.shared.b16 {%0,%1,%2,%3}, [%4];"
                 : "=r"(r0), "=r"(r1), "=r"(r2), "=r"(r3) : "r"(addr));
}

__device__ __forceinline__ void mma_bf16(float& c0, float& c1, float& c2, float& c3,
                                         uint32_t a0, uint32_t a1, uint32_t a2, uint32_t a3,
                                         uint32_t b0, uint32_t b1) {
    asm volatile("mma.sync.aligned.m16n8k16.row.col.f32.bf16.bf16.f32 "
                 "{%0,%1,%2,%3}, {%4,%5,%6,%7}, {%8,%9}, {%0,%1,%2,%3};"
                 : "+f"(c0), "+f"(c1), "+f"(c2), "+f"(c3)
                 : "r"(a0), "r"(a1), "r"(a2), "r"(a3), "r"(b0), "r"(b1));
}

__device__ __forceinline__ void cp_async16(uint32_t smem_addr, const void* gptr) {
    asm volatile("cp.async.cg.shared.global [%0], [%1], 16;"
                 :: "r"(smem_addr), "l"(gptr));
}
__device__ __forceinline__ void cp_commit() {
    asm volatile("cp.async.commit_group;");
}
__device__ __forceinline__ void cp_wait0() {
    asm volatile("cp.async.wait_group 0;" ::: "memory");
}

__device__ __forceinline__ uint32_t pack_bf2(float a, float b) {
    __nv_bfloat162 p = __floats2bfloat162_rn(a, b);
    return *reinterpret_cast<const uint32_t*>(&p);
}

// Issue cp.async for one tile: 4096 16B chunks, chunk = i*THREADS + tid.
// Rows past the segment end are clamped to the last valid row (masked later).
__device__ __forceinline__ void issue_tile(const float* __restrict__ xg,
                                           int base, int cnt, int tid,
                                           uint32_t xs_base) {
    int nrows = cnt - base;            // > 0 guaranteed by caller
    int last  = nrows - 1;
#pragma unroll
    for (int i = 0; i < 16; ++i) {
        int chunk = i * THREADS + tid;        // 0..4095
        int rowL  = chunk >> 6;               // /64 chunks per row
        int col   = (chunk & 63) * 4;         // float index
        int r     = rowL < nrows ? rowL : last;
        const float* src = xg + (size_t)(base + r) * D_IN + col;
        cp_async16(xs_base + (uint32_t)chunk * 16u, src);
    }
    cp_commit();
}

// ---------------------------------------------------------------------------
// Main kernel: one block per segment, 256 threads = 8 warps (2 row x 4 col).
// Per tile: cp.wait+bar -> convert (vectorized, 8-col octets) -> bar ->
// issue(t+1) -> mma -> epilogue (gate partials direct-store / local acc) ->
// bar -> gate_w = exp(gate) (no max: gates are O(0.3)) -> bar -> att replay.
// ---------------------------------------------------------------------------
__global__ void __launch_bounds__(THREADS, 1)
msr_main_kernel(const float* __restrict__ x,
                const float* __restrict__ b1,
                const float* __restrict__ w2,
                const float* __restrict__ b2p,
                const float* __restrict__ lpb,
                float* __restrict__ out)
{
    extern __shared__ unsigned char sm[];
    uint2* Wp      = reinterpret_cast<uint2*>(sm);
    float* Xs      = reinterpret_cast<float*>(sm + XS_OFF);
    float* gp      = reinterpret_cast<float*>(sm + SMALL_OFF);        // [2][64]
    float* gate_w  = gp + 128;                                         // [64]
    float* local_s = gate_w + 64;                                      // [128]
    float* dstage  = local_s + 128;                                    // [8]

    const int g   = blockIdx.x;
    const int tid = threadIdx.x;
    const int s0  = g_segoff[g];
    const int s1  = g_segoff[g + 1];
    const int cnt = s1 - s0;

    float* orow = out + (size_t)g * OUT_C;
    if (cnt <= 0) {
        for (int c = tid; c < OUT_C; c += THREADS) {
            orow[c] = (c >= 256 && c < 512) ? -INFINITY : 0.0f;
        }
        return;
    }

    const uint32_t xs_base  = (uint32_t)__cvta_generic_to_shared(sm + XS_OFF);
    const uint32_t abf_base = (uint32_t)__cvta_generic_to_shared(sm + ABF_OFF);
    const float* xg = x + (size_t)s0 * D_IN;

    // prologue: start fetching tile 0 immediately, then copy weights (L2-hot)
    issue_tile(xg, 0, cnt, tid, xs_base);

    for (int i = tid; i < NFRAGS; i += THREADS) Wp[i] = g_wpack[i];
    if (tid < 128) local_s[tid] = 0.0f;

    const float b2v = b2p[0];
    const int warp = tid >> 5;
    const int lane = tid & 31;
    const int wr = warp >> 2;          // 0/1  -> row block
    const int wc = warp & 3;           // 0..3 -> col block (64 cols)
    const int colbase = wc * 64;
    const bool isGate = (wc < 2);
    const int mrow0 = wr * 32;

    float biasr[16], multr[16];
#pragma unroll
    for (int ni = 0; ni < 8; ++ni) {
#pragma unroll
        for (int j = 0; j < 2; ++j) {
            int col = colbase + ni * 8 + 2 * (lane & 3) + j;
            if (isGate) { biasr[ni * 2 + j] = b1[col]; multr[ni * 2 + j] = w2[col]; }
            else        { biasr[ni * 2 + j] = lpb[col - 128]; multr[ni * 2 + j] = 0.0f; }
        }
    }

    float localacc[16];
#pragma unroll
    for (int i = 0; i < 16; ++i) localacc[i] = 0.0f;

    // convert/att ownership: warp = row-phase (rows warp, warp+8, ...),
    // lane = col octet (cols lane*8 .. lane*8+7)
    float S[8], cs[8], cm[8];
#pragma unroll
    for (int j = 0; j < 8; ++j) { S[j] = 0.0f; cs[j] = 0.0f; cm[j] = -INFINITY; }
    float dacc = 0.0f;

    // ---- tile loop --------------------------------------------------------
    for (int t0 = 0; t0 < cnt; t0 += TM) {
        const int rows = min(TM, cnt - t0);

        cp_wait0();
        __syncthreads();   // Xs(t) complete; prev att-replay done (bf16 free)

        // convert: Xs fp32 -> sum/max regs + swizzled bf16 tile (vectorized)
#pragma unroll
        for (int i = 0; i < 8; ++i) {
            int r = warp + i * 8;
            float4 va = make_float4(0.f, 0.f, 0.f, 0.f);
            float4 vb = make_float4(0.f, 0.f, 0.f, 0.f);
            if (r < rows) {
                const float* src = Xs + r * D_IN + lane * 8;
                va = *reinterpret_cast<const float4*>(src);
                vb = *reinterpret_cast<const float4*>(src + 4);
                cs[0] += va.x; cs[1] += va.y; cs[2] += va.z; cs[3] += va.w;
                cs[4] += vb.x; cs[5] += vb.y; cs[6] += vb.z; cs[7] += vb.w;
                cm[0] = fmaxf(cm[0], va.x); cm[1] = fmaxf(cm[1], va.y);
                cm[2] = fmaxf(cm[2], va.z); cm[3] = fmaxf(cm[3], va.w);
                cm[4] = fmaxf(cm[4], vb.x); cm[5] = fmaxf(cm[5], vb.y);
                cm[6] = fmaxf(cm[6], vb.z); cm[7] = fmaxf(cm[7], vb.w);
            }
            uint4 bv;
            bv.x = pack_bf2(va.x, va.y); bv.y = pack_bf2(va.z, va.w);
            bv.z = pack_bf2(vb.x, vb.y); bv.w = pack_bf2(vb.z, vb.w);
            *reinterpret_cast<uint4*>(sm + ABF_OFF + (uint32_t)r * 512u
                + (((uint32_t)lane ^ ((uint32_t)r & 7u)) << 4)) = bv;
        }
        __syncthreads();   // bf16 ready, Xs free

        // stage next tile while tensor/epilogue work runs
        if (t0 + TM < cnt) issue_tile(xg, t0 + TM, cnt, tid, xs_base);

        // MMA: [64 x 256] x [256 x 256]
        float acc[2][8][4];
#pragma unroll
        for (int mi = 0; mi < 2; ++mi)
#pragma unroll
            for (int ni = 0; ni < 8; ++ni)
#pragma unroll
                for (int q = 0; q < 4; ++q) acc[mi][ni][q] = 0.0f;

#pragma unroll
        for (int kt = 0; kt < 16; ++kt) {
            uint32_t a0[4], a1[4];
            {
                int rr = mrow0 + (lane & 15);
                uint32_t chunk = (uint32_t)(kt * 2 + (lane >> 4));
                uint32_t ad0 = abf_base + (uint32_t)rr * 512u
                               + ((chunk ^ ((uint32_t)rr & 7u)) << 4);
                ldm_x4(a0[0], a0[1], a0[2], a0[3], ad0);
                rr += 16;
                uint32_t ad1 = abf_base + (uint32_t)rr * 512u
                               + ((chunk ^ ((uint32_t)rr & 7u)) << 4);
                ldm_x4(a1[0], a1[1], a1[2], a1[3], ad1);
            }
#pragma unroll
            for (int ni = 0; ni < 8; ++ni) {
                uint2 bb = Wp[((kt * 32) + (wc * 8 + ni)) * 32 + lane];
                mma_bf16(acc[0][ni][0], acc[0][ni][1], acc[0][ni][2], acc[0][ni][3],
                         a0[0], a0[1], a0[2], a0[3], bb.x, bb.y);
                mma_bf16(acc[1][ni][0], acc[1][ni][1], acc[1][ni][2], acc[1][ni][3],
                         a1[0], a1[1], a1[2], a1[3], bb.x, bb.y);
            }
        }

        // epilogue
        if (isGate) {
            // per-row partial gate: direct store to gp[wc][r] (no atomics)
#pragma unroll
            for (int mi = 0; mi < 2; ++mi) {
#pragma unroll
                for (int q = 0; q < 2; ++q) {
                    int r = mrow0 + 16 * mi + 8 * q + (lane >> 2);
                    float p = 0.0f;
#pragma unroll
                    for (int ni = 0; ni < 8; ++ni) {
#pragma unroll
                        for (int j = 0; j < 2; ++j) {
                            float v = acc[mi][ni][q * 2 + j] + biasr[ni * 2 + j];
                            p += gelu_f(v) * multr[ni * 2 + j];
                        }
                    }
                    p += __shfl_xor_sync(0xffffffffu, p, 1);
                    p += __shfl_xor_sync(0xffffffffu, p, 2);
                    if ((lane & 3) == 0) gp[wc * 64 + r] = p;
                }
            }
        } else {
#pragma unroll
            for (int ni = 0; ni < 8; ++ni) {
#pragma unroll
                for (int j = 0; j < 2; ++j) {
                    float p = 0.0f;
#pragma unroll
                    for (int mi = 0; mi < 2; ++mi) {
#pragma unroll
                        for (int q = 0; q < 2; ++q) {
                            int r = mrow0 + 16 * mi + 8 * q + (lane >> 2);
                            if (r < rows)
                                p += gelu_f(acc[mi][ni][q * 2 + j] + biasr[ni * 2 + j]);
                        }
                    }
                    localacc[ni * 2 + j] += p;
                }
            }
        }
        __syncthreads();

        // gate weights: plain exp, no max subtraction (gates are O(0.3);
        // softmax is shift-invariant so this is mathematically identical)
        if (tid < TM) {
            gate_w[tid] = (tid < rows)
                ? __expf(gp[tid] + gp[64 + tid] + b2v) : 0.0f;
        }
        __syncthreads();

        // attention accumulation (bf16 tile replay, vectorized);
        // invalid rows have weight 0 so loop is uniform
#pragma unroll
        for (int i = 0; i < 8; ++i) {
            int r = warp + i * 8;
            float w = gate_w[r];
            uint4 pv = *reinterpret_cast<const uint4*>(
                sm + ABF_OFF + (uint32_t)r * 512u
                + (((uint32_t)lane ^ ((uint32_t)r & 7u)) << 4));
            float2 f0 = __bfloat1622float2(*reinterpret_cast<__nv_bfloat162*>(&pv.x));
            float2 f1 = __bfloat1622float2(*reinterpret_cast<__nv_bfloat162*>(&pv.y));
            float2 f2 = __bfloat1622float2(*reinterpret_cast<__nv_bfloat162*>(&pv.z));
            float2 f3 = __bfloat1622float2(*reinterpret_cast<__nv_bfloat162*>(&pv.w));
            S[0] = fmaf(w, f0.x, S[0]); S[1] = fmaf(w, f0.y, S[1]);
            S[2] = fmaf(w, f1.x, S[2]); S[3] = fmaf(w, f1.y, S[3]);
            S[4] = fmaf(w, f2.x, S[4]); S[5] = fmaf(w, f2.y, S[5]);
            S[6] = fmaf(w, f3.x, S[6]); S[7] = fmaf(w, f3.y, S[7]);
            if (lane == 0) dacc += w;
        }
        // next loop iteration's cp_wait0 + __syncthreads separates replay
        // from the next convert's overwrite of ABF / gate_w / gp
    }
    __syncthreads();

    // ---- final reductions & output ---------------------------------------
    // local channels: butterfly over the 8 lanes sharing each column
#pragma unroll
    for (int i = 0; i < 16; ++i) {
        float v = localacc[i];
        v += __shfl_xor_sync(0xffffffffu, v, 4);
        v += __shfl_xor_sync(0xffffffffu, v, 8);
        v += __shfl_xor_sync(0xffffffffu, v, 16);
        localacc[i] = v;
    }
    if (!isGate && (lane >> 2) == 0) {
#pragma unroll
        for (int ni = 0; ni < 8; ++ni) {
#pragma unroll
            for (int j = 0; j < 2; ++j) {
                int cl = colbase - 128 + ni * 8 + 2 * (lane & 3) + j;
                atomicAdd(&local_s[cl], localacc[ni * 2 + j]);
            }
        }
    }
    if (lane == 0) dstage[warp] = dacc;
    __syncthreads();

    // stage per-thread partials in (now free) Xs: 8 row-phase reps per column
    float* red = Xs;   // [3][256][8]
#pragma unroll
    for (int j = 0; j < 8; ++j) {
        int col = lane * 8 + j;
        red[col * 8 + warp]        = cs[j];
        red[2048 + col * 8 + warp] = cm[j];
        red[4096 + col * 8 + warp] = S[j];
    }
    __syncthreads();

    {
        const float cntf = (float)cnt;
        float d = dstage[0] + dstage[1] + dstage[2] + dstage[3]
                + dstage[4] + dstage[5] + dstage[6] + dstage[7];
        int col = tid;
        float s = 0.0f, mx = -INFINITY, a = 0.0f;
#pragma unroll
        for (int rep = 0; rep < 8; ++rep) {
            s += red[col * 8 + rep];
            mx = fmaxf(mx, red[2048 + col * 8 + rep]);
            a += red[4096 + col * 8 + rep];
        }
        orow[col]       = s / cntf;
        orow[256 + col] = mx;
        orow[512 + col] = a / d;
        if (tid < 128) orow[768 + tid] = local_s[tid] / cntf;
    }
}

// ---------------------------------------------------------------------------
// Launch: 2 launches per replay.
// ---------------------------------------------------------------------------
extern "C" void kernel_launch(void* const* d_in, const int* in_sizes, int n_in,
                              void* d_out, int out_size) {
    const float* x    = (const float*)d_in[0];
    const int*   bat  = (const int*)  d_in[1];
    const float* w1   = (const float*)d_in[2];
    const float* b1   = (const float*)d_in[3];
    const float* w2   = (const float*)d_in[4];
    const float* b2   = (const float*)d_in[5];
    const float* lpw  = (const float*)d_in[6];
    const float* lpb  = (const float*)d_in[7];
    float* out = (float*)d_out;

    int n = in_sizes[0] / D_IN;

    cudaFuncSetAttribute(msr_main_kernel,
                         cudaFuncAttributeMaxDynamicSharedMemorySize, SMEM_BYTES);

    int prep_threads = NFRAGS + n;
    prep_kernel<<<(prep_threads + 255) / 256, 256>>>(bat, n, w1, lpw);
    msr_main_kernel<<<G_SEG, THREADS, SMEM_BYTES>>>(x, b1, w2, b2, lpb, out);
}

// round 16
// speedup vs baseline: 2.0855x; 1.2121x over previous
#include <cuda_runtime.h>
#include <cuda_bf16.h>
#include <math.h>
#include <stdint.h>

#define D_IN    256
#define G_SEG   1024
#define H_HID   128
#define OUT_C   896
#define TM      64
#define THREADS 256
#define NFRAGS  (16*32*32)            /* k-tiles * n-tiles * lanes */

/* SMEM: XS fp32 staging | ABF bf16 tile | small+biases. 100352B -> 2 CTAs/SM */
#define XS_OFF     0
#define XS_BYTES   (TM*D_IN*4)                /* 65536 */
#define ABF_OFF    (XS_OFF + XS_BYTES)        /* 65536 */
#define ABF_BYTES  (TM*512)                   /* 32768 */
#define SMALL_OFF  (ABF_OFF + ABF_BYTES)      /* 98304 */
#define SMEM_BYTES (SMALL_OFF + 4096)         /* 100352 */

__device__ int   g_segoff[G_SEG + 1];
__device__ uint2 g_wpack[NFRAGS];             /* L2-resident, shared by all CTAs */

// ---------------------------------------------------------------------------
// Prep kernel (single launch): weight frag pack + segment offsets.
// ---------------------------------------------------------------------------
__global__ void prep_kernel(const int* __restrict__ batch, int n,
                            const float* __restrict__ w1,
                            const float* __restrict__ lpw) {
    int idx = blockIdx.x * blockDim.x + threadIdx.x;
    if (idx < NFRAGS) {
        int lane = idx & 31;
        int nt   = (idx >> 5) & 31;
        int kt   = idx >> 10;
        int nn = nt * 8 + (lane >> 2);
        int k0 = kt * 16 + (lane & 3) * 2;
        const float* W = (nn < H_HID) ? w1 : lpw;
        int nc = nn & 127;
        float v0 = W[(k0    ) * H_HID + nc];
        float v1 = W[(k0 + 1) * H_HID + nc];
        float v2 = W[(k0 + 8) * H_HID + nc];
        float v3 = W[(k0 + 9) * H_HID + nc];
        __nv_bfloat162 p0 = __floats2bfloat162_rn(v0, v1);
        __nv_bfloat162 p1 = __floats2bfloat162_rn(v2, v3);
        uint2 u;
        u.x = *reinterpret_cast<const uint32_t*>(&p0);
        u.y = *reinterpret_cast<const uint32_t*>(&p1);
        g_wpack[idx] = u;
    } else {
        int i = idx - NFRAGS;
        if (i < n) {
            int b  = batch[i];
            int pb = (i == 0) ? -1 : batch[i - 1];
            for (int s = pb + 1; s <= b; ++s) g_segoff[s] = i;
            if (i == n - 1)
                for (int s = b + 1; s <= G_SEG; ++s) g_segoff[s] = n;
        }
    }
}

// ---------------------------------------------------------------------------
// Helpers
// ---------------------------------------------------------------------------
// tanh-form GELU using HW tanh.approx (pre-activations here have |v| < ~2).
__device__ __forceinline__ float gelu_f(float v) {
    float u = 0.79788456080286536f * fmaf(0.044715f * v, v * v, v);
    float t;
    asm("tanh.approx.f32 %0, %1;" : "=f"(t) : "f"(u));
    return 0.5f * v * (1.0f + t);
}

__device__ __forceinline__ void ldm_x4(uint32_t& r0, uint32_t& r1,
                                       uint32_t& r2, uint32_t& r3,
                                       uint32_t addr) {
    asm volatile("ldmatrix.sync.aligned.m8n8.x4.shared.b16 {%0,%1,%2,%3}, [%4];"
                 : "=r"(r0), "=r"(r1), "=r"(r2), "=r"(r3) : "r"(addr));
}

__device__ __forceinline__ void mma_bf16(float& c0, float& c1, float& c2, float& c3,
                                         uint32_t a0, uint32_t a1, uint32_t a2, uint32_t a3,
                                         uint32_t b0, uint32_t b1) {
    asm volatile("mma.sync.aligned.m16n8k16.row.col.f32.bf16.bf16.f32 "
                 "{%0,%1,%2,%3}, {%4,%5,%6,%7}, {%8,%9}, {%0,%1,%2,%3};"
                 : "+f"(c0), "+f"(c1), "+f"(c2), "+f"(c3)
                 : "r"(a0), "r"(a1), "r"(a2), "r"(a3), "r"(b0), "r"(b1));
}

__device__ __forceinline__ void cp_async16(uint32_t smem_addr, const void* gptr) {
    asm volatile("cp.async.cg.shared.global [%0], [%1], 16;"
                 :: "r"(smem_addr), "l"(gptr));
}
__device__ __forceinline__ void cp_commit() {
    asm volatile("cp.async.commit_group;");
}
__device__ __forceinline__ void cp_wait0() {
    asm volatile("cp.async.wait_group 0;" ::: "memory");
}

__device__ __forceinline__ uint32_t pack_bf2(float a, float b) {
    __nv_bfloat162 p = __floats2bfloat162_rn(a, b);
    return *reinterpret_cast<const uint32_t*>(&p);
}

// Issue cp.async for one tile: 4096 16B chunks, chunk = i*THREADS + tid.
// Rows past the segment end are clamped to the last valid row (masked later).
__device__ __forceinline__ void issue_tile(const float* __restrict__ xg,
                                           int base, int cnt, int tid,
                                           uint32_t xs_base) {
    int nrows = cnt - base;            // > 0 guaranteed by caller
    int last  = nrows - 1;
#pragma unroll
    for (int i = 0; i < 16; ++i) {
        int chunk = i * THREADS + tid;        // 0..4095
        int rowL  = chunk >> 6;               // /64 chunks per row
        int col   = (chunk & 63) * 4;         // float index
        int r     = rowL < nrows ? rowL : last;
        const float* src = xg + (size_t)(base + r) * D_IN + col;
        cp_async16(xs_base + (uint32_t)chunk * 16u, src);
    }
    cp_commit();
}

// ---------------------------------------------------------------------------
// Main kernel: one block per segment, 256 threads = 8 warps (2 row x 4 col).
// 2 CTAs/SM (98KB smem): co-resident segments interleave their phase chains.
// Weights are read per-mma from L2-resident g_wpack (no smem copy).
// MMA is split into two N-half passes (acc 32 regs) to fit the 128-reg cap
// imposed by __launch_bounds__(256, 2) without spilling.
// ---------------------------------------------------------------------------
__global__ void __launch_bounds__(THREADS, 2)
msr_main_kernel(const float* __restrict__ x,
                const float* __restrict__ b1,
                const float* __restrict__ w2,
                const float* __restrict__ b2p,
                const float* __restrict__ lpb,
                float* __restrict__ out)
{
    extern __shared__ unsigned char sm[];
    float* Xs      = reinterpret_cast<float*>(sm + XS_OFF);
    float* gp      = reinterpret_cast<float*>(sm + SMALL_OFF);        // [2][64]
    float* gate_w  = gp + 128;                                         // [64]
    float* local_s = gate_w + 64;                                      // [128]
    float* dstage  = local_s + 128;                                    // [8]
    float* b1s     = dstage + 8;                                       // [128]
    float* w2s     = b1s + 128;                                        // [128]
    float* lpbs    = w2s + 128;                                        // [128]

    const int g   = blockIdx.x;
    const int tid = threadIdx.x;
    const int s0  = g_segoff[g];
    const int s1  = g_segoff[g + 1];
    const int cnt = s1 - s0;

    float* orow = out + (size_t)g * OUT_C;
    if (cnt <= 0) {
        for (int c = tid; c < OUT_C; c += THREADS) {
            orow[c] = (c >= 256 && c < 512) ? -INFINITY : 0.0f;
        }
        return;
    }

    const uint32_t xs_base  = (uint32_t)__cvta_generic_to_shared(sm + XS_OFF);
    const uint32_t abf_base = (uint32_t)__cvta_generic_to_shared(sm + ABF_OFF);
    const float* xg = x + (size_t)s0 * D_IN;

    // prologue: start fetching tile 0 immediately
    issue_tile(xg, 0, cnt, tid, xs_base);

    if (tid < 128) {
        local_s[tid] = 0.0f;
        b1s[tid]  = b1[tid];
        w2s[tid]  = w2[tid];
        lpbs[tid] = lpb[tid];
    }

    const float b2v = b2p[0];
    const int warp = tid >> 5;
    const int lane = tid & 31;
    const int wr = warp >> 2;          // 0/1  -> row block
    const int wc = warp & 3;           // 0..3 -> col block (64 cols)
    const int colbase = wc * 64;
    const bool isGate = (wc < 2);
    const int mrow0 = wr * 32;

    float localacc[16];
#pragma unroll
    for (int i = 0; i < 16; ++i) localacc[i] = 0.0f;

    // convert/att ownership: warp = row-phase (rows warp, warp+8, ...),
    // lane = col octet (cols lane*8 .. lane*8+7)
    float S[8], cs[8], cm[8];
#pragma unroll
    for (int j = 0; j < 8; ++j) { S[j] = 0.0f; cs[j] = 0.0f; cm[j] = -INFINITY; }
    float dacc = 0.0f;

    __syncthreads();   // local_s / bias tables ready

    // ---- tile loop --------------------------------------------------------
    for (int t0 = 0; t0 < cnt; t0 += TM) {
        const int rows = min(TM, cnt - t0);

        cp_wait0();
        __syncthreads();   // Xs(t) complete; prev att-replay done (bf16 free)

        // convert: Xs fp32 -> sum/max regs + swizzled bf16 tile (vectorized)
#pragma unroll
        for (int i = 0; i < 8; ++i) {
            int r = warp + i * 8;
            float4 va = make_float4(0.f, 0.f, 0.f, 0.f);
            float4 vb = make_float4(0.f, 0.f, 0.f, 0.f);
            if (r < rows) {
                const float* src = Xs + r * D_IN + lane * 8;
                va = *reinterpret_cast<const float4*>(src);
                vb = *reinterpret_cast<const float4*>(src + 4);
                cs[0] += va.x; cs[1] += va.y; cs[2] += va.z; cs[3] += va.w;
                cs[4] += vb.x; cs[5] += vb.y; cs[6] += vb.z; cs[7] += vb.w;
                cm[0] = fmaxf(cm[0], va.x); cm[1] = fmaxf(cm[1], va.y);
                cm[2] = fmaxf(cm[2], va.z); cm[3] = fmaxf(cm[3], va.w);
                cm[4] = fmaxf(cm[4], vb.x); cm[5] = fmaxf(cm[5], vb.y);
                cm[6] = fmaxf(cm[6], vb.z); cm[7] = fmaxf(cm[7], vb.w);
            }
            uint4 bv;
            bv.x = pack_bf2(va.x, va.y); bv.y = pack_bf2(va.z, va.w);
            bv.z = pack_bf2(vb.x, vb.y); bv.w = pack_bf2(vb.z, vb.w);
            *reinterpret_cast<uint4*>(sm + ABF_OFF + (uint32_t)r * 512u
                + (((uint32_t)lane ^ ((uint32_t)r & 7u)) << 4)) = bv;
        }
        __syncthreads();   // bf16 ready, Xs free

        // stage next tile while tensor/epilogue work runs
        if (t0 + TM < cnt) issue_tile(xg, t0 + TM, cnt, tid, xs_base);

        // gate row-partials, carried across the two N-half passes
        float prow[4] = {0.0f, 0.0f, 0.0f, 0.0f};

#pragma unroll
        for (int half = 0; half < 2; ++half) {
            // hoist this half's 8 bias/mult constants from smem
            float bias8[8], mult8[8];
#pragma unroll
            for (int e = 0; e < 8; ++e) {
                int col = colbase + (half * 4 + (e >> 1)) * 8
                          + 2 * (lane & 3) + (e & 1);
                if (isGate) { bias8[e] = b1s[col]; mult8[e] = w2s[col]; }
                else        { bias8[e] = lpbs[col - 128]; mult8[e] = 0.0f; }
            }

            float acc[2][4][4];
#pragma unroll
            for (int mi = 0; mi < 2; ++mi)
#pragma unroll
                for (int ni = 0; ni < 4; ++ni)
#pragma unroll
                    for (int q = 0; q < 4; ++q) acc[mi][ni][q] = 0.0f;

            const uint2* wbase = g_wpack + (size_t)(wc * 8 + half * 4) * 32 + lane;
#pragma unroll
            for (int kt = 0; kt < 16; ++kt) {
                uint32_t a0[4], a1[4];
                {
                    int rr = mrow0 + (lane & 15);
                    uint32_t chunk = (uint32_t)(kt * 2 + (lane >> 4));
                    uint32_t ad0 = abf_base + (uint32_t)rr * 512u
                                   + ((chunk ^ ((uint32_t)rr & 7u)) << 4);
                    ldm_x4(a0[0], a0[1], a0[2], a0[3], ad0);
                    rr += 16;
                    uint32_t ad1 = abf_base + (uint32_t)rr * 512u
                                   + ((chunk ^ ((uint32_t)rr & 7u)) << 4);
                    ldm_x4(a1[0], a1[1], a1[2], a1[3], ad1);
                }
#pragma unroll
                for (int ni = 0; ni < 4; ++ni) {
                    uint2 bb = __ldg(wbase + (size_t)(kt * 32 + ni) * 32);
                    mma_bf16(acc[0][ni][0], acc[0][ni][1], acc[0][ni][2], acc[0][ni][3],
                             a0[0], a0[1], a0[2], a0[3], bb.x, bb.y);
                    mma_bf16(acc[1][ni][0], acc[1][ni][1], acc[1][ni][2], acc[1][ni][3],
                             a1[0], a1[1], a1[2], a1[3], bb.x, bb.y);
                }
            }

            // epilogue for this half
            if (isGate) {
#pragma unroll
                for (int mi = 0; mi < 2; ++mi) {
#pragma unroll
                    for (int q = 0; q < 2; ++q) {
                        float p = 0.0f;
#pragma unroll
                        for (int ni = 0; ni < 4; ++ni) {
#pragma unroll
                            for (int j = 0; j < 2; ++j) {
                                float v = acc[mi][ni][q * 2 + j] + bias8[ni * 2 + j];
                                p += gelu_f(v) * mult8[ni * 2 + j];
                            }
                        }
                        prow[mi * 2 + q] += p;
                    }
                }
            } else {
#pragma unroll
                for (int ni = 0; ni < 4; ++ni) {
#pragma unroll
                    for (int j = 0; j < 2; ++j) {
                        float p = 0.0f;
#pragma unroll
                        for (int mi = 0; mi < 2; ++mi) {
#pragma unroll
                            for (int q = 0; q < 2; ++q) {
                                int r = mrow0 + 16 * mi + 8 * q + (lane >> 2);
                                if (r < rows)
                                    p += gelu_f(acc[mi][ni][q * 2 + j] + bias8[ni * 2 + j]);
                            }
                        }
                        localacc[(half * 4 + ni) * 2 + j] += p;
                    }
                }
            }
        }

        // gate: reduce row-partials across the 4 lanes of each row group
        if (isGate) {
#pragma unroll
            for (int mi = 0; mi < 2; ++mi) {
#pragma unroll
                for (int q = 0; q < 2; ++q) {
                    float p = prow[mi * 2 + q];
                    p += __shfl_xor_sync(0xffffffffu, p, 1);
                    p += __shfl_xor_sync(0xffffffffu, p, 2);
                    int r = mrow0 + 16 * mi + 8 * q + (lane >> 2);
                    if ((lane & 3) == 0) gp[wc * 64 + r] = p;
                }
            }
        }
        __syncthreads();

        // gate weights: plain exp, no max subtraction (gates are O(0.3);
        // softmax is shift-invariant so this is mathematically identical)
        if (tid < TM) {
            gate_w[tid] = (tid < rows)
                ? __expf(gp[tid] + gp[64 + tid] + b2v) : 0.0f;
        }
        __syncthreads();

        // attention accumulation (bf16 tile replay, vectorized);
        // invalid rows have weight 0 so loop is uniform
#pragma unroll
        for (int i = 0; i < 8; ++i) {
            int r = warp + i * 8;
            float w = gate_w[r];
            uint4 pv = *reinterpret_cast<const uint4*>(
                sm + ABF_OFF + (uint32_t)r * 512u
                + (((uint32_t)lane ^ ((uint32_t)r & 7u)) << 4));
            float2 f0 = __bfloat1622float2(*reinterpret_cast<__nv_bfloat162*>(&pv.x));
            float2 f1 = __bfloat1622float2(*reinterpret_cast<__nv_bfloat162*>(&pv.y));
            float2 f2 = __bfloat1622float2(*reinterpret_cast<__nv_bfloat162*>(&pv.z));
            float2 f3 = __bfloat1622float2(*reinterpret_cast<__nv_bfloat162*>(&pv.w));
            S[0] = fmaf(w, f0.x, S[0]); S[1] = fmaf(w, f0.y, S[1]);
            S[2] = fmaf(w, f1.x, S[2]); S[3] = fmaf(w, f1.y, S[3]);
            S[4] = fmaf(w, f2.x, S[4]); S[5] = fmaf(w, f2.y, S[5]);
            S[6] = fmaf(w, f3.x, S[6]); S[7] = fmaf(w, f3.y, S[7]);
            if (lane == 0) dacc += w;
        }
        // next loop iteration's cp_wait0 + __syncthreads separates replay
        // from the next convert's overwrite of ABF / gate_w / gp
    }
    __syncthreads();

    // ---- final reductions & output ---------------------------------------
    // local channels: butterfly over the 8 lanes sharing each column
#pragma unroll
    for (int i = 0; i < 16; ++i) {
        float v = localacc[i];
        v += __shfl_xor_sync(0xffffffffu, v, 4);
        v += __shfl_xor_sync(0xffffffffu, v, 8);
        v += __shfl_xor_sync(0xffffffffu, v, 16);
        localacc[i] = v;
    }
    if (!isGate && (lane >> 2) == 0) {
#pragma unroll
        for (int ni = 0; ni < 8; ++ni) {
#pragma unroll
            for (int j = 0; j < 2; ++j) {
                int cl = colbase - 128 + ni * 8 + 2 * (lane & 3) + j;
                atomicAdd(&local_s[cl], localacc[ni * 2 + j]);
            }
        }
    }
    if (lane == 0) dstage[warp] = dacc;
    __syncthreads();

    // stage per-thread partials in (now free) Xs: 8 row-phase reps per column
    float* red = Xs;   // [3][256][8]
#pragma unroll
    for (int j = 0; j < 8; ++j) {
        int col = lane * 8 + j;
        red[col * 8 + warp]        = cs[j];
        red[2048 + col * 8 + warp] = cm[j];
        red[4096 + col * 8 + warp] = S[j];
    }
    __syncthreads();

    {
        const float cntf = (float)cnt;
        float d = dstage[0] + dstage[1] + dstage[2] + dstage[3]
                + dstage[4] + dstage[5] + dstage[6] + dstage[7];
        int col = tid;
        float s = 0.0f, mx = -INFINITY, a = 0.0f;
#pragma unroll
        for (int rep = 0; rep < 8; ++rep) {
            s += red[col * 8 + rep];
            mx = fmaxf(mx, red[2048 + col * 8 + rep]);
            a += red[4096 + col * 8 + rep];
        }
        orow[col]       = s / cntf;
        orow[256 + col] = mx;
        orow[512 + col] = a / d;
        if (tid < 128) orow[768 + tid] = local_s[tid] / cntf;
    }
}

// ---------------------------------------------------------------------------
// Launch: 2 launches per replay.
// ---------------------------------------------------------------------------
extern "C" void kernel_launch(void* const* d_in, const int* in_sizes, int n_in,
                              void* d_out, int out_size) {
    const float* x    = (const float*)d_in[0];
    const int*   bat  = (const int*)  d_in[1];
    const float* w1   = (const float*)d_in[2];
    const float* b1   = (const float*)d_in[3];
    const float* w2   = (const float*)d_in[4];
    const float* b2   = (const float*)d_in[5];
    const float* lpw  = (const float*)d_in[6];
    const float* lpb  = (const float*)d_in[7];
    float* out = (float*)d_out;

    int n = in_sizes[0] / D_IN;

    cudaFuncSetAttribute(msr_main_kernel,
                         cudaFuncAttributeMaxDynamicSharedMemorySize, SMEM_BYTES);

    int prep_threads = NFRAGS + n;
    prep_kernel<<<(prep_threads + 255) / 256, 256>>>(bat, n, w1, lpw);
    msr_main_kernel<<<G_SEG, THREADS, SMEM_BYTES>>>(x, b1, w2, b2, lpb, out);
}

// round 17
// speedup vs baseline: 2.2395x; 1.0738x over previous
#include <cuda_runtime.h>
#include <cuda_bf16.h>
#include <cuda_fp16.h>
#include <math.h>
#include <stdint.h>

#define D_IN    256
#define G_SEG   1024
#define H_HID   128
#define OUT_C   896
#define TM      64
#define THREADS 256
#define NPAIR4  8192           /* 16 kt * 8 (wc,half) * 2 p * 32 lanes uint4 */

/* SMEM: XS fp32 staging | ABF bf16 tile | small+biases. 100352B -> 2 CTAs/SM */
#define XS_OFF     0
#define XS_BYTES   (TM*D_IN*4)                /* 65536 */
#define ABF_OFF    (XS_OFF + XS_BYTES)        /* 65536 */
#define ABF_BYTES  (TM*512)                   /* 32768 */
#define SMALL_OFF  (ABF_OFF + ABF_BYTES)      /* 98304 */
#define SMEM_BYTES (SMALL_OFF + 4096)         /* 100352 */

__device__ int   g_segoff[G_SEG + 1];
__device__ uint4 g_wpack4[NPAIR4];            /* L2-resident, shared by all CTAs */

// ---------------------------------------------------------------------------
// Prep kernel: weight frag pack (paired for LDG.128) + segment offsets.
// uint4 e: lane=e&31, p=(e>>5)&1, half=(e>>6)&1, wc=(e>>7)&3, kt=e>>9.
// Covers frags nt0=wc*8+half*4+2p and nt0+1: {f(nt0).x,.y, f(nt0+1).x,.y}.
// ---------------------------------------------------------------------------
__global__ void prep_kernel(const int* __restrict__ batch, int n,
                            const float* __restrict__ w1,
                            const float* __restrict__ lpw) {
    int idx = blockIdx.x * blockDim.x + threadIdx.x;
    if (idx < NPAIR4) {
        int lane = idx & 31;
        int p    = (idx >> 5) & 1;
        int half = (idx >> 6) & 1;
        int wc   = (idx >> 7) & 3;
        int kt   = idx >> 9;
        int k0 = kt * 16 + (lane & 3) * 2;
        uint4 u;
#pragma unroll
        for (int s = 0; s < 2; ++s) {
            int nt = wc * 8 + half * 4 + 2 * p + s;
            int nn = nt * 8 + (lane >> 2);
            const float* W = (nn < H_HID) ? w1 : lpw;
            int nc = nn & 127;
            float v0 = W[(k0    ) * H_HID + nc];
            float v1 = W[(k0 + 1) * H_HID + nc];
            float v2 = W[(k0 + 8) * H_HID + nc];
            float v3 = W[(k0 + 9) * H_HID + nc];
            __nv_bfloat162 p0 = __floats2bfloat162_rn(v0, v1);
            __nv_bfloat162 p1 = __floats2bfloat162_rn(v2, v3);
            if (s == 0) {
                u.x = *reinterpret_cast<const uint32_t*>(&p0);
                u.y = *reinterpret_cast<const uint32_t*>(&p1);
            } else {
                u.z = *reinterpret_cast<const uint32_t*>(&p0);
                u.w = *reinterpret_cast<const uint32_t*>(&p1);
            }
        }
        g_wpack4[idx] = u;
    } else {
        int i = idx - NPAIR4;
        if (i < n) {
            int b  = batch[i];
            int pb = (i == 0) ? -1 : batch[i - 1];
            for (int s = pb + 1; s <= b; ++s) g_segoff[s] = i;
            if (i == n - 1)
                for (int s = b + 1; s <= G_SEG; ++s) g_segoff[s] = n;
        }
    }
}

// ---------------------------------------------------------------------------
// Helpers
// ---------------------------------------------------------------------------
// tanh-form GELU on packed f16x2 (HW tanh.approx.f16x2); |v| < ~3 here.
__device__ __forceinline__ __half2 gelu_h2(__half2 v) {
    __half2 v2 = __hmul2(v, v);
    __half2 t1 = __hfma2(v2, __float2half2_rn(0.0356774081f),
                         __float2half2_rn(0.7978845608f));
    __half2 u  = __hmul2(v, t1);
    uint32_t tu = *reinterpret_cast<uint32_t*>(&u), tt;
    asm("tanh.approx.f16x2 %0, %1;" : "=r"(tt) : "r"(tu));
    __half2 t  = *reinterpret_cast<__half2*>(&tt);
    __half2 hv = __hmul2(v, __float2half2_rn(0.5f));
    return __hfma2(t, hv, hv);
}

__device__ __forceinline__ void ldm_x4(uint32_t& r0, uint32_t& r1,
                                       uint32_t& r2, uint32_t& r3,
                                       uint32_t addr) {
    asm volatile("ldmatrix.sync.aligned.m8n8.x4.shared.b16 {%0,%1,%2,%3}, [%4];"
                 : "=r"(r0), "=r"(r1), "=r"(r2), "=r"(r3) : "r"(addr));
}

__device__ __forceinline__ void mma_bf16(float& c0, float& c1, float& c2, float& c3,
                                         uint32_t a0, uint32_t a1, uint32_t a2, uint32_t a3,
                                         uint32_t b0, uint32_t b1) {
    asm volatile("mma.sync.aligned.m16n8k16.row.col.f32.bf16.bf16.f32 "
                 "{%0,%1,%2,%3}, {%4,%5,%6,%7}, {%8,%9}, {%0,%1,%2,%3};"
                 : "+f"(c0), "+f"(c1), "+f"(c2), "+f"(c3)
                 : "r"(a0), "r"(a1), "r"(a2), "r"(a3), "r"(b0), "r"(b1));
}

__device__ __forceinline__ void cp_async16(uint32_t smem_addr, const void* gptr) {
    asm volatile("cp.async.cg.shared.global [%0], [%1], 16;"
                 :: "r"(smem_addr), "l"(gptr));
}
__device__ __forceinline__ void cp_commit() {
    asm volatile("cp.async.commit_group;");
}
__device__ __forceinline__ void cp_wait0() {
    asm volatile("cp.async.wait_group 0;" ::: "memory");
}

__device__ __forceinline__ uint32_t pack_bf2(float a, float b) {
    __nv_bfloat162 p = __floats2bfloat162_rn(a, b);
    return *reinterpret_cast<const uint32_t*>(&p);
}

// Issue cp.async for one tile: 4096 16B chunks, chunk = i*THREADS + tid.
// Rows past the segment end are clamped to the last valid row (masked later).
__device__ __forceinline__ void issue_tile(const float* __restrict__ xg,
                                           int base, int cnt, int tid,
                                           uint32_t xs_base) {
    int nrows = cnt - base;            // > 0 guaranteed by caller
    int last  = nrows - 1;
#pragma unroll
    for (int i = 0; i < 16; ++i) {
        int chunk = i * THREADS + tid;        // 0..4095
        int rowL  = chunk >> 6;               // /64 chunks per row
        int col   = (chunk & 63) * 4;         // float index
        int r     = rowL < nrows ? rowL : last;
        const float* src = xg + (size_t)(base + r) * D_IN + col;
        cp_async16(xs_base + (uint32_t)chunk * 16u, src);
    }
    cp_commit();
}

// ---------------------------------------------------------------------------
// Main kernel: one block per segment, 256 threads = 8 warps (2 row x 4 col).
// 2 CTAs/SM; weights streamed from L2 via paired LDG.128; f16x2 gelu
// epilogues with hoisted packed constants.
// ---------------------------------------------------------------------------
__global__ void __launch_bounds__(THREADS, 2)
msr_main_kernel(const float* __restrict__ x,
                const float* __restrict__ b1,
                const float* __restrict__ w2,
                const float* __restrict__ b2p,
                const float* __restrict__ lpb,
                float* __restrict__ out)
{
    extern __shared__ unsigned char sm[];
    float* Xs      = reinterpret_cast<float*>(sm + XS_OFF);
    float* gp      = reinterpret_cast<float*>(sm + SMALL_OFF);        // [2][64]
    float* gate_w  = gp + 128;                                         // [64]
    float* local_s = gate_w + 64;                                      // [128]
    float* dstage  = local_s + 128;                                    // [8]
    float* b1s     = dstage + 8;                                       // [128]
    float* w2s     = b1s + 128;                                        // [128]
    float* lpbs    = w2s + 128;                                        // [128]

    const int g   = blockIdx.x;
    const int tid = threadIdx.x;
    const int s0  = g_segoff[g];
    const int s1  = g_segoff[g + 1];
    const int cnt = s1 - s0;

    float* orow = out + (size_t)g * OUT_C;
    if (cnt <= 0) {
        for (int c = tid; c < OUT_C; c += THREADS) {
            orow[c] = (c >= 256 && c < 512) ? -INFINITY : 0.0f;
        }
        return;
    }

    const uint32_t xs_base  = (uint32_t)__cvta_generic_to_shared(sm + XS_OFF);
    const uint32_t abf_base = (uint32_t)__cvta_generic_to_shared(sm + ABF_OFF);
    const float* xg = x + (size_t)s0 * D_IN;

    // prologue: start fetching tile 0 immediately
    issue_tile(xg, 0, cnt, tid, xs_base);

    if (tid < 128) {
        local_s[tid] = 0.0f;
        b1s[tid]  = b1[tid];
        w2s[tid]  = w2[tid];
        lpbs[tid] = lpb[tid];
    }

    const float b2v = b2p[0];
    const int warp = tid >> 5;
    const int lane = tid & 31;
    const int wr = warp >> 2;          // 0/1  -> row block
    const int wc = warp & 3;           // 0..3 -> col block (64 cols)
    const int colbase = wc * 64;
    const bool isGate = (wc < 2);
    const int mrow0 = wr * 32;

    float localacc[16];
#pragma unroll
    for (int i = 0; i < 16; ++i) localacc[i] = 0.0f;

    // convert/att ownership: warp = row-phase (rows warp, warp+8, ...),
    // lane = col octet (cols lane*8 .. lane*8+7)
    float S[8], cs[8], cm[8];
#pragma unroll
    for (int j = 0; j < 8; ++j) { S[j] = 0.0f; cs[j] = 0.0f; cm[j] = -INFINITY; }
    float dacc = 0.0f;

    __syncthreads();   // local_s / bias tables ready

    // hoisted packed epilogue constants: bh/mh[half*4+ni] for column pair
    __half2 bh[8], mh[8];
#pragma unroll
    for (int e = 0; e < 8; ++e) {
        int col0 = colbase + e * 8 + 2 * (lane & 3);
        if (isGate) {
            bh[e] = __floats2half2_rn(b1s[col0], b1s[col0 + 1]);
            mh[e] = __floats2half2_rn(w2s[col0], w2s[col0 + 1]);
        } else {
            bh[e] = __floats2half2_rn(lpbs[col0 - 128], lpbs[col0 - 127]);
            mh[e] = __float2half2_rn(0.0f);
        }
    }

    // ---- tile loop --------------------------------------------------------
    for (int t0 = 0; t0 < cnt; t0 += TM) {
        const int rows = min(TM, cnt - t0);

        cp_wait0();
        __syncthreads();   // Xs(t) complete; prev att-replay done (bf16 free)

        // convert: Xs fp32 -> sum/max regs + swizzled bf16 tile (vectorized)
#pragma unroll
        for (int i = 0; i < 8; ++i) {
            int r = warp + i * 8;
            float4 va = make_float4(0.f, 0.f, 0.f, 0.f);
            float4 vb = make_float4(0.f, 0.f, 0.f, 0.f);
            if (r < rows) {
                const float* src = Xs + r * D_IN + lane * 8;
                va = *reinterpret_cast<const float4*>(src);
                vb = *reinterpret_cast<const float4*>(src + 4);
                cs[0] += va.x; cs[1] += va.y; cs[2] += va.z; cs[3] += va.w;
                cs[4] += vb.x; cs[5] += vb.y; cs[6] += vb.z; cs[7] += vb.w;
                cm[0] = fmaxf(cm[0], va.x); cm[1] = fmaxf(cm[1], va.y);
                cm[2] = fmaxf(cm[2], va.z); cm[3] = fmaxf(cm[3], va.w);
                cm[4] = fmaxf(cm[4], vb.x); cm[5] = fmaxf(cm[5], vb.y);
                cm[6] = fmaxf(cm[6], vb.z); cm[7] = fmaxf(cm[7], vb.w);
            }
            uint4 bv;
            bv.x = pack_bf2(va.x, va.y); bv.y = pack_bf2(va.z, va.w);
            bv.z = pack_bf2(vb.x, vb.y); bv.w = pack_bf2(vb.z, vb.w);
            *reinterpret_cast<uint4*>(sm + ABF_OFF + (uint32_t)r * 512u
                + (((uint32_t)lane ^ ((uint32_t)r & 7u)) << 4)) = bv;
        }
        __syncthreads();   // bf16 ready, Xs free

        // stage next tile while tensor/epilogue work runs
        if (t0 + TM < cnt) issue_tile(xg, t0 + TM, cnt, tid, xs_base);

        // gate row-partials, carried across the two N-half passes
        float prow[4] = {0.0f, 0.0f, 0.0f, 0.0f};

#pragma unroll
        for (int half = 0; half < 2; ++half) {
            float acc[2][4][4];
#pragma unroll
            for (int mi = 0; mi < 2; ++mi)
#pragma unroll
                for (int ni = 0; ni < 4; ++ni)
#pragma unroll
                    for (int q = 0; q < 4; ++q) acc[mi][ni][q] = 0.0f;

            // paired weight base for this (wc, half): two uint4 per kt
            const uint4* wb = g_wpack4 + (size_t)(wc * 2 + half) * 64 + lane;
#pragma unroll
            for (int kt = 0; kt < 16; ++kt) {
                uint32_t a0[4], a1[4];
                {
                    int rr = mrow0 + (lane & 15);
                    uint32_t chunk = (uint32_t)(kt * 2 + (lane >> 4));
                    uint32_t ad0 = abf_base + (uint32_t)rr * 512u
                                   + ((chunk ^ ((uint32_t)rr & 7u)) << 4);
                    ldm_x4(a0[0], a0[1], a0[2], a0[3], ad0);
                    rr += 16;
                    uint32_t ad1 = abf_base + (uint32_t)rr * 512u
                                   + ((chunk ^ ((uint32_t)rr & 7u)) << 4);
                    ldm_x4(a1[0], a1[1], a1[2], a1[3], ad1);
                }
                uint4 q0 = __ldg(wb + (size_t)kt * 512);
                uint4 q1 = __ldg(wb + (size_t)kt * 512 + 32);
                mma_bf16(acc[0][0][0], acc[0][0][1], acc[0][0][2], acc[0][0][3],
                         a0[0], a0[1], a0[2], a0[3], q0.x, q0.y);
                mma_bf16(acc[1][0][0], acc[1][0][1], acc[1][0][2], acc[1][0][3],
                         a1[0], a1[1], a1[2], a1[3], q0.x, q0.y);
                mma_bf16(acc[0][1][0], acc[0][1][1], acc[0][1][2], acc[0][1][3],
                         a0[0], a0[1], a0[2], a0[3], q0.z, q0.w);
                mma_bf16(acc[1][1][0], acc[1][1][1], acc[1][1][2], acc[1][1][3],
                         a1[0], a1[1], a1[2], a1[3], q0.z, q0.w);
                mma_bf16(acc[0][2][0], acc[0][2][1], acc[0][2][2], acc[0][2][3],
                         a0[0], a0[1], a0[2], a0[3], q1.x, q1.y);
                mma_bf16(acc[1][2][0], acc[1][2][1], acc[1][2][2], acc[1][2][3],
                         a1[0], a1[1], a1[2], a1[3], q1.x, q1.y);
                mma_bf16(acc[0][3][0], acc[0][3][1], acc[0][3][2], acc[0][3][3],
                         a0[0], a0[1], a0[2], a0[3], q1.z, q1.w);
                mma_bf16(acc[1][3][0], acc[1][3][1], acc[1][3][2], acc[1][3][3],
                         a1[0], a1[1], a1[2], a1[3], q1.z, q1.w);
            }

            // epilogue for this half (f16x2 gelu)
            if (isGate) {
#pragma unroll
                for (int mi = 0; mi < 2; ++mi) {
#pragma unroll
                    for (int q = 0; q < 2; ++q) {
                        __half2 pa = __float2half2_rn(0.0f);
#pragma unroll
                        for (int ni = 0; ni < 4; ++ni) {
                            __half2 v = __floats2half2_rn(acc[mi][ni][q * 2],
                                                          acc[mi][ni][q * 2 + 1]);
                            v = __hadd2(v, bh[half * 4 + ni]);
                            pa = __hfma2(gelu_h2(v), mh[half * 4 + ni], pa);
                        }
                        prow[mi * 2 + q] += __low2float(pa) + __high2float(pa);
                    }
                }
            } else {
#pragma unroll
                for (int ni = 0; ni < 4; ++ni) {
                    __half2 pa = __float2half2_rn(0.0f);
#pragma unroll
                    for (int mi = 0; mi < 2; ++mi) {
#pragma unroll
                        for (int q = 0; q < 2; ++q) {
                            int r = mrow0 + 16 * mi + 8 * q + (lane >> 2);
                            if (r < rows) {
                                __half2 v = __floats2half2_rn(acc[mi][ni][q * 2],
                                                              acc[mi][ni][q * 2 + 1]);
                                v = __hadd2(v, bh[half * 4 + ni]);
                                pa = __hadd2(pa, gelu_h2(v));
                            }
                        }
                    }
                    localacc[(half * 4 + ni) * 2 + 0] += __low2float(pa);
                    localacc[(half * 4 + ni) * 2 + 1] += __high2float(pa);
                }
            }
        }

        // gate: reduce row-partials across the 4 lanes of each row group
        if (isGate) {
#pragma unroll
            for (int mi = 0; mi < 2; ++mi) {
#pragma unroll
                for (int q = 0; q < 2; ++q) {
                    float p = prow[mi * 2 + q];
                    p += __shfl_xor_sync(0xffffffffu, p, 1);
                    p += __shfl_xor_sync(0xffffffffu, p, 2);
                    int r = mrow0 + 16 * mi + 8 * q + (lane >> 2);
                    if ((lane & 3) == 0) gp[wc * 64 + r] = p;
                }
            }
        }
        __syncthreads();

        // gate weights: plain exp, no max subtraction (gates are O(0.3);
        // softmax is shift-invariant so this is mathematically identical)
        if (tid < TM) {
            gate_w[tid] = (tid < rows)
                ? __expf(gp[tid] + gp[64 + tid] + b2v) : 0.0f;
        }
        __syncthreads();

        // attention accumulation (bf16 tile replay, vectorized);
        // invalid rows have weight 0 so loop is uniform
#pragma unroll
        for (int i = 0; i < 8; ++i) {
            int r = warp + i * 8;
            float w = gate_w[r];
            uint4 pv = *reinterpret_cast<const uint4*>(
                sm + ABF_OFF + (uint32_t)r * 512u
                + (((uint32_t)lane ^ ((uint32_t)r & 7u)) << 4));
            float2 f0 = __bfloat1622float2(*reinterpret_cast<__nv_bfloat162*>(&pv.x));
            float2 f1 = __bfloat1622float2(*reinterpret_cast<__nv_bfloat162*>(&pv.y));
            float2 f2 = __bfloat1622float2(*reinterpret_cast<__nv_bfloat162*>(&pv.z));
            float2 f3 = __bfloat1622float2(*reinterpret_cast<__nv_bfloat162*>(&pv.w));
            S[0] = fmaf(w, f0.x, S[0]); S[1] = fmaf(w, f0.y, S[1]);
            S[2] = fmaf(w, f1.x, S[2]); S[3] = fmaf(w, f1.y, S[3]);
            S[4] = fmaf(w, f2.x, S[4]); S[5] = fmaf(w, f2.y, S[5]);
            S[6] = fmaf(w, f3.x, S[6]); S[7] = fmaf(w, f3.y, S[7]);
            if (lane == 0) dacc += w;
        }
        // next loop iteration's cp_wait0 + __syncthreads separates replay
        // from the next convert's overwrite of ABF / gate_w / gp
    }
    __syncthreads();

    // ---- final reductions & output ---------------------------------------
    // local channels: butterfly over the 8 lanes sharing each column
#pragma unroll
    for (int i = 0; i < 16; ++i) {
        float v = localacc[i];
        v += __shfl_xor_sync(0xffffffffu, v, 4);
        v += __shfl_xor_sync(0xffffffffu, v, 8);
        v += __shfl_xor_sync(0xffffffffu, v, 16);
        localacc[i] = v;
    }
    if (!isGate && (lane >> 2) == 0) {
#pragma unroll
        for (int ni = 0; ni < 8; ++ni) {
#pragma unroll
            for (int j = 0; j < 2; ++j) {
                int cl = colbase - 128 + ni * 8 + 2 * (lane & 3) + j;
                atomicAdd(&local_s[cl], localacc[ni * 2 + j]);
            }
        }
    }
    if (lane == 0) dstage[warp] = dacc;
    __syncthreads();

    // stage per-thread partials in (now free) Xs: 8 row-phase reps per column
    float* red = Xs;   // [3][256][8]
#pragma unroll
    for (int j = 0; j < 8; ++j) {
        int col = lane * 8 + j;
        red[col * 8 + warp]        = cs[j];
        red[2048 + col * 8 + warp] = cm[j];
        red[4096 + col * 8 + warp] = S[j];
    }
    __syncthreads();

    {
        const float cntf = (float)cnt;
        float d = dstage[0] + dstage[1] + dstage[2] + dstage[3]
                + dstage[4] + dstage[5] + dstage[6] + dstage[7];
        int col = tid;
        float s = 0.0f, mx = -INFINITY, a = 0.0f;
#pragma unroll
        for (int rep = 0; rep < 8; ++rep) {
            s += red[col * 8 + rep];
            mx = fmaxf(mx, red[2048 + col * 8 + rep]);
            a += red[4096 + col * 8 + rep];
        }
        orow[col]       = s / cntf;
        orow[256 + col] = mx;
        orow[512 + col] = a / d;
        if (tid < 128) orow[768 + tid] = local_s[tid] / cntf;
    }
}

// ---------------------------------------------------------------------------
// Launch: 2 launches per replay.
// ---------------------------------------------------------------------------
extern "C" void kernel_launch(void* const* d_in, const int* in_sizes, int n_in,
                              void* d_out, int out_size) {
    const float* x    = (const float*)d_in[0];
    const int*   bat  = (const int*)  d_in[1];
    const float* w1   = (const float*)d_in[2];
    const float* b1   = (const float*)d_in[3];
    const float* w2   = (const float*)d_in[4];
    const float* b2   = (const float*)d_in[5];
    const float* lpw  = (const float*)d_in[6];
    const float* lpb  = (const float*)d_in[7];
    float* out = (float*)d_out;

    int n = in_sizes[0] / D_IN;

    cudaFuncSetAttribute(msr_main_kernel,
                         cudaFuncAttributeMaxDynamicSharedMemorySize, SMEM_BYTES);

    int prep_threads = NPAIR4 + n;
    prep_kernel<<<(prep_threads + 255) / 256, 256>>>(bat, n, w1, lpw);
    msr_main_kernel<<<G_SEG, THREADS, SMEM_BYTES>>>(x, b1, w2, b2, lpb, out);
}